// round 1
// baseline (speedup 1.0000x reference)
#include <cuda_runtime.h>
#include <cstdint>

#define D_MODEL   768
#define NUM_HEADS 12
#define D_K       64
#define BATCH     4
#define SEQ       2048
#define M_TOTAL   (BATCH * SEQ)   // 8192

// ---------------- scratch (no allocations allowed) ----------------
__device__ float g_Q[M_TOTAL * D_MODEL];
__device__ float g_K[M_TOTAL * D_MODEL];
__device__ float g_V[M_TOTAL * D_MODEL];
__device__ float g_O[M_TOTAL * D_MODEL];

// =================================================================
// GEMM:  C[M,768] = A[M,768] @ W[768,768]^T + bias   (torch Linear)
// Block tile 128x64, BK=16, 256 threads, 8x4 micro-tile per thread.
// =================================================================
#define GB_BM 128
#define GB_BN 64
#define GB_BK 16

__global__ __launch_bounds__(256) void gemm_bias(
    const float* __restrict__ A, const float* __restrict__ W,
    const float* __restrict__ bias, float* __restrict__ C)
{
    __shared__ float As[GB_BK][GB_BM];   // k-major
    __shared__ float Ws[GB_BK][GB_BN];   // k-major

    const int tid = threadIdx.x;
    const int tx  = tid & 15;        // 0..15 -> n group (4 cols)
    const int ty  = tid >> 4;        // 0..15 -> m group (8 rows)
    const int row0 = blockIdx.y * GB_BM;
    const int col0 = blockIdx.x * GB_BN;

    float acc[8][4];
#pragma unroll
    for (int i = 0; i < 8; ++i)
#pragma unroll
        for (int j = 0; j < 4; ++j) acc[i][j] = 0.f;

    for (int k0 = 0; k0 < D_MODEL; k0 += GB_BK) {
        // ---- load A tile (128x16) : 512 float4 slots, 2 per thread ----
#pragma unroll
        for (int p = 0; p < 2; ++p) {
            int s = p * 256 + tid;
            int r = s >> 2;              // 0..127
            int c = (s & 3) << 2;        // 0,4,8,12
            float4 v = *(const float4*)(A + (size_t)(row0 + r) * D_MODEL + k0 + c);
            As[c + 0][r] = v.x; As[c + 1][r] = v.y;
            As[c + 2][r] = v.z; As[c + 3][r] = v.w;
        }
        // ---- load W tile (64x16) : 256 float4 slots, 1 per thread ----
        {
            int s = tid;
            int n = s >> 2;              // 0..63
            int c = (s & 3) << 2;
            float4 v = *(const float4*)(W + (size_t)(col0 + n) * D_MODEL + k0 + c);
            Ws[c + 0][n] = v.x; Ws[c + 1][n] = v.y;
            Ws[c + 2][n] = v.z; Ws[c + 3][n] = v.w;
        }
        __syncthreads();

#pragma unroll
        for (int kk = 0; kk < GB_BK; ++kk) {
            float4 a0 = *(const float4*)&As[kk][ty * 8];
            float4 a1 = *(const float4*)&As[kk][ty * 8 + 4];
            float4 bv = *(const float4*)&Ws[kk][tx * 4];
            float a[8] = {a0.x, a0.y, a0.z, a0.w, a1.x, a1.y, a1.z, a1.w};
            float b[4] = {bv.x, bv.y, bv.z, bv.w};
#pragma unroll
            for (int i = 0; i < 8; ++i)
#pragma unroll
                for (int j = 0; j < 4; ++j)
                    acc[i][j] = fmaf(a[i], b[j], acc[i][j]);
        }
        __syncthreads();
    }

    const int col = col0 + tx * 4;
    float4 bv = *(const float4*)(bias + col);
#pragma unroll
    for (int i = 0; i < 8; ++i) {
        int row = row0 + ty * 8 + i;
        float4 o;
        o.x = acc[i][0] + bv.x;
        o.y = acc[i][1] + bv.y;
        o.z = acc[i][2] + bv.z;
        o.w = acc[i][3] + bv.w;
        *(float4*)(C + (size_t)row * D_MODEL + col) = o;
    }
}

// =================================================================
// Flash attention: one CTA per (b, h, 64-row q tile).
// Qt/Kt stored d-major with 4-float-granule XOR swizzle.
// P tile reuses the K buffer. Online softmax state in registers,
// replicated across the 16 lanes of each row-group via shfl.
// =================================================================
__global__ __launch_bounds__(256) void flash_attn(
    const float* __restrict__ Qg, const float* __restrict__ Kg,
    const float* __restrict__ Vg, float* __restrict__ Og)
{
    __shared__ float Qt[64 * 64];   // [d][swizzled q]
    __shared__ float KP[64 * 64];   // K: [d][swizzled k]  then  P: [q][k]
    __shared__ float Vs[64 * 64];   // [k][d]

    const int tid = threadIdx.x;
    const int tx  = tid & 15;       // k-group / d-group (4 cols)
    const int ty  = tid >> 4;       // q-group (4 rows)
    const int q0  = blockIdx.x * 64;
    const int h   = blockIdx.y;
    const int b   = blockIdx.z;
    const size_t base = (size_t)b * SEQ * D_MODEL + h * 64;

    // ---- load Q (64x64) transposed + swizzled, pre-scaled by 1/sqrt(Dk) ----
#pragma unroll
    for (int p = 0; p < 4; ++p) {
        int s = p * 256 + tid;
        int r = s >> 4;              // q row 0..63
        int c = (s & 15) << 2;       // d 0..60
        float4 v = *(const float4*)(Qg + base + (size_t)(q0 + r) * D_MODEL + c);
        float vals[4] = {v.x, v.y, v.z, v.w};
#pragma unroll
        for (int u = 0; u < 4; ++u) {
            int d = c + u;
            Qt[d * 64 + (((r >> 2) ^ (d & 15)) << 2) + (r & 3)] = vals[u] * 0.125f;
        }
    }

    float m_i[4], l_i[4], acc[4][4];
#pragma unroll
    for (int i = 0; i < 4; ++i) {
        m_i[i] = -1e30f; l_i[i] = 0.f;
#pragma unroll
        for (int j = 0; j < 4; ++j) acc[i][j] = 0.f;
    }

    for (int kv0 = 0; kv0 < SEQ; kv0 += 64) {
        __syncthreads();   // prev tile's P/V reads done; (1st iter: Qt fence w/ next sync)

        // ---- load K transposed+swizzled, V direct ----
#pragma unroll
        for (int p = 0; p < 4; ++p) {
            int s = p * 256 + tid;
            int r = s >> 4;
            int c = (s & 15) << 2;
            float4 kv = *(const float4*)(Kg + base + (size_t)(kv0 + r) * D_MODEL + c);
            float kvals[4] = {kv.x, kv.y, kv.z, kv.w};
#pragma unroll
            for (int u = 0; u < 4; ++u) {
                int d = c + u;
                KP[d * 64 + (((r >> 2) ^ (d & 15)) << 2) + (r & 3)] = kvals[u];
            }
            float4 vv = *(const float4*)(Vg + base + (size_t)(kv0 + r) * D_MODEL + c);
            *(float4*)&Vs[r * 64 + c] = vv;
        }
        __syncthreads();

        // ---- S = Q K^T  (4x4 per thread over d=64) ----
        float sc[4][4];
#pragma unroll
        for (int i = 0; i < 4; ++i)
#pragma unroll
            for (int j = 0; j < 4; ++j) sc[i][j] = 0.f;

#pragma unroll 8
        for (int d = 0; d < 64; ++d) {
            float4 aq = *(const float4*)&Qt[d * 64 + ((ty ^ (d & 15)) << 2)];
            float4 bk = *(const float4*)&KP[d * 64 + ((tx ^ (d & 15)) << 2)];
            float a[4] = {aq.x, aq.y, aq.z, aq.w};
            float kb[4] = {bk.x, bk.y, bk.z, bk.w};
#pragma unroll
            for (int i = 0; i < 4; ++i)
#pragma unroll
                for (int j = 0; j < 4; ++j)
                    sc[i][j] = fmaf(a[i], kb[j], sc[i][j]);
        }

        // ---- online softmax (register state, shfl over 16-lane row groups) ----
        float pr[4][4], corr[4];
#pragma unroll
        for (int i = 0; i < 4; ++i) {
            float t = fmaxf(fmaxf(sc[i][0], sc[i][1]), fmaxf(sc[i][2], sc[i][3]));
#pragma unroll
            for (int off = 1; off < 16; off <<= 1)
                t = fmaxf(t, __shfl_xor_sync(0xffffffffu, t, off));
            float mn = fmaxf(m_i[i], t);
            corr[i] = __expf(m_i[i] - mn);
            m_i[i] = mn;
            float rs = 0.f;
#pragma unroll
            for (int j = 0; j < 4; ++j) {
                pr[i][j] = __expf(sc[i][j] - mn);
                rs += pr[i][j];
            }
#pragma unroll
            for (int off = 1; off < 16; off <<= 1)
                rs += __shfl_xor_sync(0xffffffffu, rs, off);
            l_i[i] = l_i[i] * corr[i] + rs;
#pragma unroll
            for (int j = 0; j < 4; ++j) acc[i][j] *= corr[i];
        }

        __syncthreads();   // all K reads done before P overwrites the buffer
#pragma unroll
        for (int i = 0; i < 4; ++i) {
            float4 pv = make_float4(pr[i][0], pr[i][1], pr[i][2], pr[i][3]);
            *(float4*)&KP[(ty * 4 + i) * 64 + tx * 4] = pv;
        }
        __syncthreads();

        // ---- O += P V  (inner over k=64) ----
#pragma unroll 4
        for (int k4 = 0; k4 < 64; k4 += 4) {
            float prow[4][4];
#pragma unroll
            for (int i = 0; i < 4; ++i)
                *(float4*)prow[i] = *(const float4*)&KP[(ty * 4 + i) * 64 + k4];
#pragma unroll
            for (int u = 0; u < 4; ++u) {
                float4 vv = *(const float4*)&Vs[(k4 + u) * 64 + tx * 4];
                float vb[4] = {vv.x, vv.y, vv.z, vv.w};
#pragma unroll
                for (int i = 0; i < 4; ++i)
#pragma unroll
                    for (int j = 0; j < 4; ++j)
                        acc[i][j] = fmaf(prow[i][u], vb[j], acc[i][j]);
            }
        }
    }

    // ---- epilogue: normalize and store ----
#pragma unroll
    for (int i = 0; i < 4; ++i) {
        float inv = 1.f / l_i[i];
        int row = q0 + ty * 4 + i;
        float4 o = make_float4(acc[i][0] * inv, acc[i][1] * inv,
                               acc[i][2] * inv, acc[i][3] * inv);
        *(float4*)(Og + base + (size_t)row * D_MODEL + tx * 4) = o;
    }
}

// =================================================================
// Launch
// =================================================================
extern "C" void kernel_launch(void* const* d_in, const int* in_sizes, int n_in,
                              void* d_out, int out_size)
{
    const float* query = (const float*)d_in[0];
    const float* key   = (const float*)d_in[1];
    const float* value = (const float*)d_in[2];
    const float* Wq = (const float*)d_in[3];
    const float* bq = (const float*)d_in[4];
    const float* Wk = (const float*)d_in[5];
    const float* bk = (const float*)d_in[6];
    const float* Wv = (const float*)d_in[7];
    const float* bv = (const float*)d_in[8];
    const float* Wo = (const float*)d_in[9];
    const float* bo = (const float*)d_in[10];
    float* out = (float*)d_out;

    float *Qb, *Kb, *Vb, *Ob;
    cudaGetSymbolAddress((void**)&Qb, g_Q);
    cudaGetSymbolAddress((void**)&Kb, g_K);
    cudaGetSymbolAddress((void**)&Vb, g_V);
    cudaGetSymbolAddress((void**)&Ob, g_O);

    dim3 ggrid(D_MODEL / GB_BN, M_TOTAL / GB_BM);   // (12, 64)
    gemm_bias<<<ggrid, 256>>>(query, Wq, bq, Qb);
    gemm_bias<<<ggrid, 256>>>(key,   Wk, bk, Kb);
    gemm_bias<<<ggrid, 256>>>(value, Wv, bv, Vb);

    dim3 agrid(SEQ / 64, NUM_HEADS, BATCH);          // (32, 12, 4)
    flash_attn<<<agrid, 256>>>(Qb, Kb, Vb, Ob);

    gemm_bias<<<ggrid, 256>>>(Ob, Wo, bo, out);
}

// round 3
// speedup vs baseline: 1.2472x; 1.2472x over previous
#include <cuda_runtime.h>
#include <cuda_bf16.h>
#include <cstdint>

#define D_MODEL   768
#define NUM_HEADS 12
#define D_K       64
#define BATCH     4
#define SEQ       2048
#define M_TOTAL   (BATCH * SEQ)   // 8192

// ---------------- scratch (no allocations allowed) ----------------
__device__ float g_Q[M_TOTAL * D_MODEL];
__device__ float g_K[M_TOTAL * D_MODEL];
__device__ float g_V[M_TOTAL * D_MODEL];
__device__ float g_O[M_TOTAL * D_MODEL];
__device__ __nv_bfloat16 g_Ahi[M_TOTAL * D_MODEL];
__device__ __nv_bfloat16 g_Alo[M_TOTAL * D_MODEL];
__device__ __nv_bfloat16 g_Whi[D_MODEL * D_MODEL];
__device__ __nv_bfloat16 g_Wlo[D_MODEL * D_MODEL];

// =================================================================
// fp32 -> (hi, lo) bf16 split
// =================================================================
__global__ __launch_bounds__(256) void split_bf16(
    const float* __restrict__ x, __nv_bfloat16* __restrict__ hi,
    __nv_bfloat16* __restrict__ lo, int n)
{
    int i = (blockIdx.x * 256 + threadIdx.x) * 4;
    if (i >= n) return;
    float4 v = *(const float4*)(x + i);
    float f[4] = {v.x, v.y, v.z, v.w};
    unsigned short h[4], l[4];
#pragma unroll
    for (int u = 0; u < 4; ++u) {
        __nv_bfloat16 hh = __float2bfloat16(f[u]);
        __nv_bfloat16 ll = __float2bfloat16(f[u] - __bfloat162float(hh));
        h[u] = *(unsigned short*)&hh;
        l[u] = *(unsigned short*)&ll;
    }
    *(ushort4*)((unsigned short*)hi + i) = make_ushort4(h[0], h[1], h[2], h[3]);
    *(ushort4*)((unsigned short*)lo + i) = make_ushort4(l[0], l[1], l[2], l[3]);
}

// =================================================================
// mma.sync m16n8k16 bf16 helper
// =================================================================
__device__ __forceinline__ void mma16816(float* c, const uint32_t* a, const uint32_t* b) {
    asm volatile(
        "mma.sync.aligned.m16n8k16.row.col.f32.bf16.bf16.f32 "
        "{%0,%1,%2,%3}, {%4,%5,%6,%7}, {%8,%9}, {%0,%1,%2,%3};"
        : "+f"(c[0]), "+f"(c[1]), "+f"(c[2]), "+f"(c[3])
        : "r"(a[0]), "r"(a[1]), "r"(a[2]), "r"(a[3]), "r"(b[0]), "r"(b[1]));
}

// =================================================================
// Tensor-core GEMM:  C[M,768] = A @ W^T + bias, 3-term bf16 split.
// CTA 128x128, 8 warps, warp tile 32x64 (2 m-frags x 8 n-frags).
// K-chunks of 32 bf16, register-prefetch pipeline.
// =================================================================
#define KC  32
#define NC  (D_MODEL / KC)     // 24 chunks
#define PAD 40                 // b16 stride per tile row (80 B)

__global__ __launch_bounds__(256) void gemm_mma(
    const __nv_bfloat16* __restrict__ Ahi, const __nv_bfloat16* __restrict__ Alo,
    const __nv_bfloat16* __restrict__ Whi, const __nv_bfloat16* __restrict__ Wlo,
    const float* __restrict__ bias, float* __restrict__ C)
{
    __shared__ __nv_bfloat16 st[4][128 * PAD];   // Ahi, Alo, Whi, Wlo tiles

    const int tid  = threadIdx.x;
    const int wid  = tid >> 5;
    const int lane = tid & 31;
    const int g    = lane >> 2;       // group id 0..7
    const int q    = lane & 3;        // thread-in-group
    const int warpM = wid & 3;        // 4 -> 32 rows each
    const int warpN = wid >> 2;       // 2 -> 64 cols each
    const int row0 = blockIdx.y * 128;
    const int col0 = blockIdx.x * 128;

    // global source rows for this thread's 2 load slots (per matrix)
    const int r_l[2]  = { (tid >> 2) + 0, (tid >> 2) + 64 };   // p*256+tid >> 2
    const int c8      = (tid & 3) * 8;

    const __nv_bfloat16* gsrc[4] = {
        Ahi + (size_t)row0 * D_MODEL,
        Alo + (size_t)row0 * D_MODEL,
        Whi + (size_t)col0 * D_MODEL,
        Wlo + (size_t)col0 * D_MODEL };

    float acc[2][8][4];
#pragma unroll
    for (int i = 0; i < 2; ++i)
#pragma unroll
        for (int j = 0; j < 8; ++j)
#pragma unroll
            for (int u = 0; u < 4; ++u) acc[i][j][u] = 0.f;

    // prefetch chunk 0
    uint4 pre[4][2];
#pragma unroll
    for (int m = 0; m < 4; ++m)
#pragma unroll
        for (int p = 0; p < 2; ++p)
            pre[m][p] = *(const uint4*)(gsrc[m] + (size_t)r_l[p] * D_MODEL + c8);

    for (int c = 0; c < NC; ++c) {
        if (c) __syncthreads();        // previous chunk's compute done
#pragma unroll
        for (int m = 0; m < 4; ++m)
#pragma unroll
            for (int p = 0; p < 2; ++p)
                *(uint4*)&st[m][r_l[p] * PAD + c8] = pre[m][p];
        // issue next chunk's loads before the barrier (overlap with compute)
        if (c + 1 < NC) {
            const int k0 = (c + 1) * KC;
#pragma unroll
            for (int m = 0; m < 4; ++m)
#pragma unroll
                for (int p = 0; p < 2; ++p)
                    pre[m][p] = *(const uint4*)(gsrc[m] + (size_t)r_l[p] * D_MODEL + k0 + c8);
        }
        __syncthreads();

        const __nv_bfloat16* As[2] = { &st[0][warpM * 32 * PAD], &st[1][warpM * 32 * PAD] };
        const __nv_bfloat16* Ws[2] = { &st[2][warpN * 64 * PAD], &st[3][warpN * 64 * PAD] };

#pragma unroll
        for (int ks = 0; ks < KC; ks += 16) {
            uint32_t a[2][2][4];   // [hi/lo][mfrag][reg]
            uint32_t b[2][8][2];   // [hi/lo][nfrag][reg]
#pragma unroll
            for (int t = 0; t < 2; ++t)
#pragma unroll
                for (int mf = 0; mf < 2; ++mf) {
                    const __nv_bfloat16* base = As[t] + (mf * 16 + g) * PAD + ks + q * 2;
                    a[t][mf][0] = *(const uint32_t*)(base);
                    a[t][mf][1] = *(const uint32_t*)(base + 8 * PAD);
                    a[t][mf][2] = *(const uint32_t*)(base + 8);
                    a[t][mf][3] = *(const uint32_t*)(base + 8 * PAD + 8);
                }
#pragma unroll
            for (int t = 0; t < 2; ++t)
#pragma unroll
                for (int nf = 0; nf < 8; ++nf) {
                    const __nv_bfloat16* base = Ws[t] + (nf * 8 + g) * PAD + ks + q * 2;
                    b[t][nf][0] = *(const uint32_t*)(base);
                    b[t][nf][1] = *(const uint32_t*)(base + 8);
                }
#pragma unroll
            for (int mf = 0; mf < 2; ++mf)
#pragma unroll
                for (int nf = 0; nf < 8; ++nf) {
                    mma16816(acc[mf][nf], a[0][mf], b[0][nf]);   // Ah*Wh
                    mma16816(acc[mf][nf], a[0][mf], b[1][nf]);   // Ah*Wl
                    mma16816(acc[mf][nf], a[1][mf], b[0][nf]);   // Al*Wh
                }
        }
    }

    // epilogue: C = acc + bias
#pragma unroll
    for (int mf = 0; mf < 2; ++mf) {
        const int row = row0 + warpM * 32 + mf * 16 + g;
#pragma unroll
        for (int nf = 0; nf < 8; ++nf) {
            const int col = col0 + warpN * 64 + nf * 8 + q * 2;
            float2 bv = *(const float2*)(bias + col);
            float2 o0 = make_float2(acc[mf][nf][0] + bv.x, acc[mf][nf][1] + bv.y);
            float2 o1 = make_float2(acc[mf][nf][2] + bv.x, acc[mf][nf][3] + bv.y);
            *(float2*)(C + (size_t)row * D_MODEL + col) = o0;
            *(float2*)(C + (size_t)(row + 8) * D_MODEL + col) = o1;
        }
    }
}

// =================================================================
// Flash attention (SIMT, unchanged from round 1)
// =================================================================
__global__ __launch_bounds__(256) void flash_attn(
    const float* __restrict__ Qg, const float* __restrict__ Kg,
    const float* __restrict__ Vg, float* __restrict__ Og)
{
    __shared__ float Qt[64 * 64];
    __shared__ float KP[64 * 64];
    __shared__ float Vs[64 * 64];

    const int tid = threadIdx.x;
    const int tx  = tid & 15;
    const int ty  = tid >> 4;
    const int q0  = blockIdx.x * 64;
    const int h   = blockIdx.y;
    const int b   = blockIdx.z;
    const size_t base = (size_t)b * SEQ * D_MODEL + h * 64;

#pragma unroll
    for (int p = 0; p < 4; ++p) {
        int s = p * 256 + tid;
        int r = s >> 4;
        int c = (s & 15) << 2;
        float4 v = *(const float4*)(Qg + base + (size_t)(q0 + r) * D_MODEL + c);
        float vals[4] = {v.x, v.y, v.z, v.w};
#pragma unroll
        for (int u = 0; u < 4; ++u) {
            int d = c + u;
            Qt[d * 64 + (((r >> 2) ^ (d & 15)) << 2) + (r & 3)] = vals[u] * 0.125f;
        }
    }

    float m_i[4], l_i[4], acc[4][4];
#pragma unroll
    for (int i = 0; i < 4; ++i) {
        m_i[i] = -1e30f; l_i[i] = 0.f;
#pragma unroll
        for (int j = 0; j < 4; ++j) acc[i][j] = 0.f;
    }

    for (int kv0 = 0; kv0 < SEQ; kv0 += 64) {
        __syncthreads();
#pragma unroll
        for (int p = 0; p < 4; ++p) {
            int s = p * 256 + tid;
            int r = s >> 4;
            int c = (s & 15) << 2;
            float4 kv = *(const float4*)(Kg + base + (size_t)(kv0 + r) * D_MODEL + c);
            float kvals[4] = {kv.x, kv.y, kv.z, kv.w};
#pragma unroll
            for (int u = 0; u < 4; ++u) {
                int d = c + u;
                KP[d * 64 + (((r >> 2) ^ (d & 15)) << 2) + (r & 3)] = kvals[u];
            }
            float4 vv = *(const float4*)(Vg + base + (size_t)(kv0 + r) * D_MODEL + c);
            *(float4*)&Vs[r * 64 + c] = vv;
        }
        __syncthreads();

        float sc[4][4];
#pragma unroll
        for (int i = 0; i < 4; ++i)
#pragma unroll
            for (int j = 0; j < 4; ++j) sc[i][j] = 0.f;

#pragma unroll 8
        for (int d = 0; d < 64; ++d) {
            float4 aq = *(const float4*)&Qt[d * 64 + ((ty ^ (d & 15)) << 2)];
            float4 bk = *(const float4*)&KP[d * 64 + ((tx ^ (d & 15)) << 2)];
            float a[4] = {aq.x, aq.y, aq.z, aq.w};
            float kb[4] = {bk.x, bk.y, bk.z, bk.w};
#pragma unroll
            for (int i = 0; i < 4; ++i)
#pragma unroll
                for (int j = 0; j < 4; ++j)
                    sc[i][j] = fmaf(a[i], kb[j], sc[i][j]);
        }

        float pr[4][4], corr[4];
#pragma unroll
        for (int i = 0; i < 4; ++i) {
            float t = fmaxf(fmaxf(sc[i][0], sc[i][1]), fmaxf(sc[i][2], sc[i][3]));
#pragma unroll
            for (int off = 1; off < 16; off <<= 1)
                t = fmaxf(t, __shfl_xor_sync(0xffffffffu, t, off));
            float mn = fmaxf(m_i[i], t);
            corr[i] = __expf(m_i[i] - mn);
            m_i[i] = mn;
            float rs = 0.f;
#pragma unroll
            for (int j = 0; j < 4; ++j) {
                pr[i][j] = __expf(sc[i][j] - mn);
                rs += pr[i][j];
            }
#pragma unroll
            for (int off = 1; off < 16; off <<= 1)
                rs += __shfl_xor_sync(0xffffffffu, rs, off);
            l_i[i] = l_i[i] * corr[i] + rs;
#pragma unroll
            for (int j = 0; j < 4; ++j) acc[i][j] *= corr[i];
        }

        __syncthreads();
#pragma unroll
        for (int i = 0; i < 4; ++i) {
            float4 pv = make_float4(pr[i][0], pr[i][1], pr[i][2], pr[i][3]);
            *(float4*)&KP[(ty * 4 + i) * 64 + tx * 4] = pv;
        }
        __syncthreads();

#pragma unroll 4
        for (int k4 = 0; k4 < 64; k4 += 4) {
            float prow[4][4];
#pragma unroll
            for (int i = 0; i < 4; ++i)
                *(float4*)prow[i] = *(const float4*)&KP[(ty * 4 + i) * 64 + k4];
#pragma unroll
            for (int u = 0; u < 4; ++u) {
                float4 vv = *(const float4*)&Vs[(k4 + u) * 64 + tx * 4];
                float vb[4] = {vv.x, vv.y, vv.z, vv.w};
#pragma unroll
                for (int i = 0; i < 4; ++i)
#pragma unroll
                    for (int j = 0; j < 4; ++j)
                        acc[i][j] = fmaf(prow[i][u], vb[j], acc[i][j]);
            }
        }
    }

#pragma unroll
    for (int i = 0; i < 4; ++i) {
        float inv = 1.f / l_i[i];
        int row = q0 + ty * 4 + i;
        float4 o = make_float4(acc[i][0] * inv, acc[i][1] * inv,
                               acc[i][2] * inv, acc[i][3] * inv);
        *(float4*)(Og + base + (size_t)row * D_MODEL + tx * 4) = o;
    }
}

// =================================================================
// Launch
// =================================================================
extern "C" void kernel_launch(void* const* d_in, const int* in_sizes, int n_in,
                              void* d_out, int out_size)
{
    const float* query = (const float*)d_in[0];
    const float* key   = (const float*)d_in[1];
    const float* value = (const float*)d_in[2];
    const float* Wq = (const float*)d_in[3];
    const float* bq = (const float*)d_in[4];
    const float* Wk = (const float*)d_in[5];
    const float* bk = (const float*)d_in[6];
    const float* Wv = (const float*)d_in[7];
    const float* bv = (const float*)d_in[8];
    const float* Wo = (const float*)d_in[9];
    const float* bo = (const float*)d_in[10];
    float* out = (float*)d_out;

    float *Qb, *Kb, *Vb, *Ob;
    __nv_bfloat16 *Ahi, *Alo, *Whi, *Wlo;
    cudaGetSymbolAddress((void**)&Qb, g_Q);
    cudaGetSymbolAddress((void**)&Kb, g_K);
    cudaGetSymbolAddress((void**)&Vb, g_V);
    cudaGetSymbolAddress((void**)&Ob, g_O);
    cudaGetSymbolAddress((void**)&Ahi, g_Ahi);
    cudaGetSymbolAddress((void**)&Alo, g_Alo);
    cudaGetSymbolAddress((void**)&Whi, g_Whi);
    cudaGetSymbolAddress((void**)&Wlo, g_Wlo);

    const int nA = M_TOTAL * D_MODEL;
    const int nW = D_MODEL * D_MODEL;
    dim3 ggrid(D_MODEL / 128, M_TOTAL / 128);   // (6, 64)

    // Q projection
    split_bf16<<<nA / 1024, 256>>>(query, Ahi, Alo, nA);
    split_bf16<<<nW / 1024, 256>>>(Wq, Whi, Wlo, nW);
    gemm_mma<<<ggrid, 256>>>(Ahi, Alo, Whi, Wlo, bq, Qb);
    // K projection
    split_bf16<<<nA / 1024, 256>>>(key, Ahi, Alo, nA);
    split_bf16<<<nW / 1024, 256>>>(Wk, Whi, Wlo, nW);
    gemm_mma<<<ggrid, 256>>>(Ahi, Alo, Whi, Wlo, bk, Kb);
    // V projection
    split_bf16<<<nA / 1024, 256>>>(value, Ahi, Alo, nA);
    split_bf16<<<nW / 1024, 256>>>(Wv, Whi, Wlo, nW);
    gemm_mma<<<ggrid, 256>>>(Ahi, Alo, Whi, Wlo, bv, Vb);

    // attention
    dim3 agrid(SEQ / 64, NUM_HEADS, BATCH);      // (32, 12, 4)
    flash_attn<<<agrid, 256>>>(Qb, Kb, Vb, Ob);

    // output projection
    split_bf16<<<nA / 1024, 256>>>(Ob, Ahi, Alo, nA);
    split_bf16<<<nW / 1024, 256>>>(Wo, Whi, Wlo, nW);
    gemm_mma<<<ggrid, 256>>>(Ahi, Alo, Whi, Wlo, bo, out);
}

// round 4
// speedup vs baseline: 2.4213x; 1.9414x over previous
#include <cuda_runtime.h>
#include <cuda_bf16.h>
#include <cstdint>

#define D_MODEL   768
#define NUM_HEADS 12
#define D_K       64
#define BATCH     4
#define SEQ       2048
#define M_TOTAL   (BATCH * SEQ)   // 8192

// ---------------- scratch (no allocations allowed) ----------------
__device__ __nv_bfloat16 g_Qhi[M_TOTAL * D_MODEL];
__device__ __nv_bfloat16 g_Qlo[M_TOTAL * D_MODEL];
__device__ __nv_bfloat16 g_Khi[M_TOTAL * D_MODEL];
__device__ __nv_bfloat16 g_Klo[M_TOTAL * D_MODEL];
__device__ __nv_bfloat16 g_Vhi[M_TOTAL * D_MODEL];
__device__ __nv_bfloat16 g_Vlo[M_TOTAL * D_MODEL];
__device__ __nv_bfloat16 g_Ahi[M_TOTAL * D_MODEL];
__device__ __nv_bfloat16 g_Alo[M_TOTAL * D_MODEL];
__device__ __nv_bfloat16 g_Whi[D_MODEL * D_MODEL];
__device__ __nv_bfloat16 g_Wlo[D_MODEL * D_MODEL];

// ---------------- small helpers ----------------
__device__ __forceinline__ uint32_t smem_u32(const void* p) {
    uint32_t a;
    asm("{ .reg .u64 t; cvta.to.shared.u64 t, %1; cvt.u32.u64 %0, t; }" : "=r"(a) : "l"(p));
    return a;
}
__device__ __forceinline__ void mma16816(float* c, const uint32_t* a, const uint32_t* b) {
    asm volatile(
        "mma.sync.aligned.m16n8k16.row.col.f32.bf16.bf16.f32 "
        "{%0,%1,%2,%3}, {%4,%5,%6,%7}, {%8,%9}, {%0,%1,%2,%3};"
        : "+f"(c[0]), "+f"(c[1]), "+f"(c[2]), "+f"(c[3])
        : "r"(a[0]), "r"(a[1]), "r"(a[2]), "r"(a[3]), "r"(b[0]), "r"(b[1]));
}
#define LDSM4T(r, addr) \
    asm volatile("ldmatrix.sync.aligned.m8n8.x4.trans.shared.b16 {%0,%1,%2,%3}, [%4];" \
        : "=r"((r)[0]), "=r"((r)[1]), "=r"((r)[2]), "=r"((r)[3]) : "r"(addr))

__device__ __forceinline__ uint32_t pack_bf16(float x, float y) {
    __nv_bfloat16 bx = __float2bfloat16(x), by = __float2bfloat16(y);
    uint16_t ux = *(uint16_t*)&bx, uy = *(uint16_t*)&by;
    return (uint32_t)ux | ((uint32_t)uy << 16);
}
__device__ __forceinline__ void split_pack2(float x, float y, uint32_t& hi, uint32_t& lo) {
    __nv_bfloat16 hx = __float2bfloat16(x), hy = __float2bfloat16(y);
    float rx = x - __bfloat162float(hx);
    float ry = y - __bfloat162float(hy);
    uint16_t a = *(uint16_t*)&hx, b = *(uint16_t*)&hy;
    hi = (uint32_t)a | ((uint32_t)b << 16);
    lo = pack_bf16(rx, ry);
}

// =================================================================
// fp32 -> (hi, lo) bf16 split (inputs + weights)
// =================================================================
__global__ __launch_bounds__(256) void split_bf16(
    const float* __restrict__ x, __nv_bfloat16* __restrict__ hi,
    __nv_bfloat16* __restrict__ lo, int n)
{
    int i = (blockIdx.x * 256 + threadIdx.x) * 4;
    if (i >= n) return;
    float4 v = *(const float4*)(x + i);
    float f[4] = {v.x, v.y, v.z, v.w};
    unsigned short h[4], l[4];
#pragma unroll
    for (int u = 0; u < 4; ++u) {
        __nv_bfloat16 hh = __float2bfloat16(f[u]);
        __nv_bfloat16 ll = __float2bfloat16(f[u] - __bfloat162float(hh));
        h[u] = *(unsigned short*)&hh;
        l[u] = *(unsigned short*)&ll;
    }
    *(ushort4*)((unsigned short*)hi + i) = make_ushort4(h[0], h[1], h[2], h[3]);
    *(ushort4*)((unsigned short*)lo + i) = make_ushort4(l[0], l[1], l[2], l[3]);
}

// =================================================================
// Tensor-core GEMM: C = A @ W^T + bias, 3-term bf16 split.
// MODE 0: write fp32 C.  MODE 1: write split bf16 (Chi, Clo).
// =================================================================
#define KC  32
#define NC  (D_MODEL / KC)
#define PAD 40

template<int MODE>
__global__ __launch_bounds__(256) void gemm_mma(
    const __nv_bfloat16* __restrict__ Ahi, const __nv_bfloat16* __restrict__ Alo,
    const __nv_bfloat16* __restrict__ Whi, const __nv_bfloat16* __restrict__ Wlo,
    const float* __restrict__ bias, float* __restrict__ C,
    __nv_bfloat16* __restrict__ Chi, __nv_bfloat16* __restrict__ Clo)
{
    __shared__ __nv_bfloat16 st[4][128 * PAD];

    const int tid  = threadIdx.x;
    const int wid  = tid >> 5;
    const int lane = tid & 31;
    const int g    = lane >> 2;
    const int q    = lane & 3;
    const int warpM = wid & 3;
    const int warpN = wid >> 2;
    const int row0 = blockIdx.y * 128;
    const int col0 = blockIdx.x * 128;

    const int r_l[2] = { (tid >> 2) + 0, (tid >> 2) + 64 };
    const int c8     = (tid & 3) * 8;

    const __nv_bfloat16* gsrc[4] = {
        Ahi + (size_t)row0 * D_MODEL, Alo + (size_t)row0 * D_MODEL,
        Whi + (size_t)col0 * D_MODEL, Wlo + (size_t)col0 * D_MODEL };

    float acc[2][8][4];
#pragma unroll
    for (int i = 0; i < 2; ++i)
#pragma unroll
        for (int j = 0; j < 8; ++j)
#pragma unroll
            for (int u = 0; u < 4; ++u) acc[i][j][u] = 0.f;

    uint4 pre[4][2];
#pragma unroll
    for (int m = 0; m < 4; ++m)
#pragma unroll
        for (int p = 0; p < 2; ++p)
            pre[m][p] = *(const uint4*)(gsrc[m] + (size_t)r_l[p] * D_MODEL + c8);

    for (int c = 0; c < NC; ++c) {
        if (c) __syncthreads();
#pragma unroll
        for (int m = 0; m < 4; ++m)
#pragma unroll
            for (int p = 0; p < 2; ++p)
                *(uint4*)&st[m][r_l[p] * PAD + c8] = pre[m][p];
        if (c + 1 < NC) {
            const int k0 = (c + 1) * KC;
#pragma unroll
            for (int m = 0; m < 4; ++m)
#pragma unroll
                for (int p = 0; p < 2; ++p)
                    pre[m][p] = *(const uint4*)(gsrc[m] + (size_t)r_l[p] * D_MODEL + k0 + c8);
        }
        __syncthreads();

        const __nv_bfloat16* As[2] = { &st[0][warpM * 32 * PAD], &st[1][warpM * 32 * PAD] };
        const __nv_bfloat16* Ws[2] = { &st[2][warpN * 64 * PAD], &st[3][warpN * 64 * PAD] };

#pragma unroll
        for (int ks = 0; ks < KC; ks += 16) {
            uint32_t a[2][2][4];
            uint32_t b[2][8][2];
#pragma unroll
            for (int t = 0; t < 2; ++t)
#pragma unroll
                for (int mf = 0; mf < 2; ++mf) {
                    const __nv_bfloat16* base = As[t] + (mf * 16 + g) * PAD + ks + q * 2;
                    a[t][mf][0] = *(const uint32_t*)(base);
                    a[t][mf][1] = *(const uint32_t*)(base + 8 * PAD);
                    a[t][mf][2] = *(const uint32_t*)(base + 8);
                    a[t][mf][3] = *(const uint32_t*)(base + 8 * PAD + 8);
                }
#pragma unroll
            for (int t = 0; t < 2; ++t)
#pragma unroll
                for (int nf = 0; nf < 8; ++nf) {
                    const __nv_bfloat16* base = Ws[t] + (nf * 8 + g) * PAD + ks + q * 2;
                    b[t][nf][0] = *(const uint32_t*)(base);
                    b[t][nf][1] = *(const uint32_t*)(base + 8);
                }
#pragma unroll
            for (int mf = 0; mf < 2; ++mf)
#pragma unroll
                for (int nf = 0; nf < 8; ++nf) {
                    mma16816(acc[mf][nf], a[0][mf], b[0][nf]);
                    mma16816(acc[mf][nf], a[0][mf], b[1][nf]);
                    mma16816(acc[mf][nf], a[1][mf], b[0][nf]);
                }
        }
    }

#pragma unroll
    for (int mf = 0; mf < 2; ++mf) {
        const int row = row0 + warpM * 32 + mf * 16 + g;
#pragma unroll
        for (int nf = 0; nf < 8; ++nf) {
            const int col = col0 + warpN * 64 + nf * 8 + q * 2;
            float2 bv = *(const float2*)(bias + col);
            float v0 = acc[mf][nf][0] + bv.x, v1 = acc[mf][nf][1] + bv.y;
            float v2 = acc[mf][nf][2] + bv.x, v3 = acc[mf][nf][3] + bv.y;
            if (MODE == 0) {
                *(float2*)(C + (size_t)row * D_MODEL + col) = make_float2(v0, v1);
                *(float2*)(C + (size_t)(row + 8) * D_MODEL + col) = make_float2(v2, v3);
            } else {
                uint32_t h0, l0, h1, l1;
                split_pack2(v0, v1, h0, l0);
                split_pack2(v2, v3, h1, l1);
                *(uint32_t*)(Chi + (size_t)row * D_MODEL + col) = h0;
                *(uint32_t*)(Clo + (size_t)row * D_MODEL + col) = l0;
                *(uint32_t*)(Chi + (size_t)(row + 8) * D_MODEL + col) = h1;
                *(uint32_t*)(Clo + (size_t)(row + 8) * D_MODEL + col) = l1;
            }
        }
    }
}

// =================================================================
// Tensor-core flash attention.
// CTA: (128 q rows, one head). 8 warps x 16 q rows. KV tiles of 64.
// 3-term split on both S = Q K^T and O = P V. P never hits SMEM.
// =================================================================
#define FPAD 72
#define FA_SMEM ((128 * 2 + 64 * 4) * FPAD * 2)   // 73728 B

__global__ __launch_bounds__(256) void flash_mma(
    const __nv_bfloat16* __restrict__ Qh_, const __nv_bfloat16* __restrict__ Ql_,
    const __nv_bfloat16* __restrict__ Kh_, const __nv_bfloat16* __restrict__ Kl_,
    const __nv_bfloat16* __restrict__ Vh_, const __nv_bfloat16* __restrict__ Vl_,
    __nv_bfloat16* __restrict__ Ohi, __nv_bfloat16* __restrict__ Olo)
{
    extern __shared__ __nv_bfloat16 sm[];
    __nv_bfloat16* sQh = sm;                 // 128 x FPAD
    __nv_bfloat16* sQl = sm + 128 * FPAD;
    __nv_bfloat16* sKh = sm + 256 * FPAD;    // 64 x FPAD each below
    __nv_bfloat16* sKl = sm + 320 * FPAD;
    __nv_bfloat16* sVh = sm + 384 * FPAD;
    __nv_bfloat16* sVl = sm + 448 * FPAD;

    const int tid = threadIdx.x, wid = tid >> 5, lane = tid & 31;
    const int g = lane >> 2, q4 = lane & 3;
    const int q0 = blockIdx.x * 128;
    const int h  = blockIdx.y;
    const int b  = blockIdx.z;
    const size_t base = (size_t)b * SEQ * D_MODEL + h * 64;

    // ---- load Q tile (128 x 64, hi+lo) ----
#pragma unroll
    for (int p = 0; p < 4; ++p) {
        int s = p * 256 + tid;
        int r = s >> 3, c = (s & 7) * 8;
        const size_t ga = base + (size_t)(q0 + r) * D_MODEL + c;
        *(uint4*)&sQh[r * FPAD + c] = *(const uint4*)(Qh_ + ga);
        *(uint4*)&sQl[r * FPAD + c] = *(const uint4*)(Ql_ + ga);
    }

    float m0 = -1e30f, m1 = -1e30f, l0 = 0.f, l1 = 0.f;
    float oacc[8][4];
#pragma unroll
    for (int j = 0; j < 8; ++j)
#pragma unroll
        for (int u = 0; u < 4; ++u) oacc[j][u] = 0.f;

    const uint32_t sbu = smem_u32(sm);
    // ldmatrix lane address components (constant over loop)
    const int lrow = (lane & 7) + ((lane >> 3) & 1) * 8;   // row within 16-k group
    const int lcol = (lane >> 4) << 3;                     // 0 or 8

    for (int kv0 = 0; kv0 < SEQ; kv0 += 64) {
        __syncthreads();
#pragma unroll
        for (int p = 0; p < 2; ++p) {
            int s = p * 256 + tid;
            int r = s >> 3, c = (s & 7) * 8;
            const size_t ga = base + (size_t)(kv0 + r) * D_MODEL + c;
            *(uint4*)&sKh[r * FPAD + c] = *(const uint4*)(Kh_ + ga);
            *(uint4*)&sKl[r * FPAD + c] = *(const uint4*)(Kl_ + ga);
            *(uint4*)&sVh[r * FPAD + c] = *(const uint4*)(Vh_ + ga);
            *(uint4*)&sVl[r * FPAD + c] = *(const uint4*)(Vl_ + ga);
        }
        __syncthreads();

        // ---- S = Q K^T ----
        float sc[8][4];
#pragma unroll
        for (int j = 0; j < 8; ++j)
#pragma unroll
            for (int u = 0; u < 4; ++u) sc[j][u] = 0.f;

#pragma unroll
        for (int kg = 0; kg < 4; ++kg) {
            uint32_t ah[4], al[4];
            const __nv_bfloat16* qb = sQh + (wid * 16 + g) * FPAD + kg * 16 + q4 * 2;
            ah[0] = *(const uint32_t*)(qb);
            ah[1] = *(const uint32_t*)(qb + 8 * FPAD);
            ah[2] = *(const uint32_t*)(qb + 8);
            ah[3] = *(const uint32_t*)(qb + 8 * FPAD + 8);
            qb = sQl + (wid * 16 + g) * FPAD + kg * 16 + q4 * 2;
            al[0] = *(const uint32_t*)(qb);
            al[1] = *(const uint32_t*)(qb + 8 * FPAD);
            al[2] = *(const uint32_t*)(qb + 8);
            al[3] = *(const uint32_t*)(qb + 8 * FPAD + 8);
#pragma unroll
            for (int nf = 0; nf < 8; ++nf) {
                const __nv_bfloat16* kb = sKh + (nf * 8 + g) * FPAD + kg * 16 + q4 * 2;
                uint32_t bh[2] = { *(const uint32_t*)(kb), *(const uint32_t*)(kb + 8) };
                kb = sKl + (nf * 8 + g) * FPAD + kg * 16 + q4 * 2;
                uint32_t bl[2] = { *(const uint32_t*)(kb), *(const uint32_t*)(kb + 8) };
                mma16816(sc[nf], ah, bh);
                mma16816(sc[nf], ah, bl);
                mma16816(sc[nf], al, bh);
            }
        }

        // ---- online softmax ----
        float t0 = -1e30f, t1 = -1e30f;
#pragma unroll
        for (int nf = 0; nf < 8; ++nf) {
#pragma unroll
            for (int u = 0; u < 4; ++u) sc[nf][u] *= 0.125f;
            t0 = fmaxf(t0, fmaxf(sc[nf][0], sc[nf][1]));
            t1 = fmaxf(t1, fmaxf(sc[nf][2], sc[nf][3]));
        }
        t0 = fmaxf(t0, __shfl_xor_sync(0xffffffffu, t0, 1));
        t0 = fmaxf(t0, __shfl_xor_sync(0xffffffffu, t0, 2));
        t1 = fmaxf(t1, __shfl_xor_sync(0xffffffffu, t1, 1));
        t1 = fmaxf(t1, __shfl_xor_sync(0xffffffffu, t1, 2));
        float mn0 = fmaxf(m0, t0), mn1 = fmaxf(m1, t1);
        float c0 = __expf(m0 - mn0), c1 = __expf(m1 - mn1);
        m0 = mn0; m1 = mn1;
        float rs0 = 0.f, rs1 = 0.f;
#pragma unroll
        for (int nf = 0; nf < 8; ++nf) {
            sc[nf][0] = __expf(sc[nf][0] - m0);
            sc[nf][1] = __expf(sc[nf][1] - m0);
            sc[nf][2] = __expf(sc[nf][2] - m1);
            sc[nf][3] = __expf(sc[nf][3] - m1);
            rs0 += sc[nf][0] + sc[nf][1];
            rs1 += sc[nf][2] + sc[nf][3];
        }
        rs0 += __shfl_xor_sync(0xffffffffu, rs0, 1);
        rs0 += __shfl_xor_sync(0xffffffffu, rs0, 2);
        rs1 += __shfl_xor_sync(0xffffffffu, rs1, 1);
        rs1 += __shfl_xor_sync(0xffffffffu, rs1, 2);
        l0 = l0 * c0 + rs0;
        l1 = l1 * c1 + rs1;
#pragma unroll
        for (int nf = 0; nf < 8; ++nf) {
            oacc[nf][0] *= c0; oacc[nf][1] *= c0;
            oacc[nf][2] *= c1; oacc[nf][3] *= c1;
        }

        // ---- O += P V ----
#pragma unroll
        for (int kg = 0; kg < 4; ++kg) {
            uint32_t pah[4], pal[4];
            split_pack2(sc[2 * kg][0],     sc[2 * kg][1],     pah[0], pal[0]);
            split_pack2(sc[2 * kg][2],     sc[2 * kg][3],     pah[1], pal[1]);
            split_pack2(sc[2 * kg + 1][0], sc[2 * kg + 1][1], pah[2], pal[2]);
            split_pack2(sc[2 * kg + 1][2], sc[2 * kg + 1][3], pah[3], pal[3]);
            const uint32_t rowoff = (uint32_t)((kg * 16 + lrow) * FPAD + lcol) * 2;
#pragma unroll
            for (int nf2 = 0; nf2 < 4; ++nf2) {
                uint32_t bh[4], bl[4];
                LDSM4T(bh, sbu + 384 * FPAD * 2 + rowoff + nf2 * 32);
                LDSM4T(bl, sbu + 448 * FPAD * 2 + rowoff + nf2 * 32);
                mma16816(oacc[2 * nf2],     pah, &bh[0]);
                mma16816(oacc[2 * nf2],     pah, &bl[0]);
                mma16816(oacc[2 * nf2],     pal, &bh[0]);
                mma16816(oacc[2 * nf2 + 1], pah, &bh[2]);
                mma16816(oacc[2 * nf2 + 1], pah, &bl[2]);
                mma16816(oacc[2 * nf2 + 1], pal, &bh[2]);
            }
        }
    }

    // ---- epilogue: normalize, split to (hi,lo) bf16 for final GEMM ----
    const float inv0 = 1.f / l0, inv1 = 1.f / l1;
    const int row0 = q0 + wid * 16 + g;
#pragma unroll
    for (int nf = 0; nf < 8; ++nf) {
        const int col = h * 64 + nf * 8 + q4 * 2;
        float v0 = oacc[nf][0] * inv0, v1 = oacc[nf][1] * inv0;
        float v2 = oacc[nf][2] * inv1, v3 = oacc[nf][3] * inv1;
        uint32_t h0, lo0, h1, lo1;
        split_pack2(v0, v1, h0, lo0);
        split_pack2(v2, v3, h1, lo1);
        *(uint32_t*)(Ohi + (size_t)(b * SEQ + row0) * D_MODEL + col) = h0;
        *(uint32_t*)(Olo + (size_t)(b * SEQ + row0) * D_MODEL + col) = lo0;
        *(uint32_t*)(Ohi + (size_t)(b * SEQ + row0 + 8) * D_MODEL + col) = h1;
        *(uint32_t*)(Olo + (size_t)(b * SEQ + row0 + 8) * D_MODEL + col) = lo1;
    }
}

// =================================================================
// Launch
// =================================================================
extern "C" void kernel_launch(void* const* d_in, const int* in_sizes, int n_in,
                              void* d_out, int out_size)
{
    const float* query = (const float*)d_in[0];
    const float* key   = (const float*)d_in[1];
    const float* value = (const float*)d_in[2];
    const float* Wq = (const float*)d_in[3];
    const float* bq = (const float*)d_in[4];
    const float* Wk = (const float*)d_in[5];
    const float* bk = (const float*)d_in[6];
    const float* Wv = (const float*)d_in[7];
    const float* bv = (const float*)d_in[8];
    const float* Wo = (const float*)d_in[9];
    const float* bo = (const float*)d_in[10];
    float* out = (float*)d_out;

    __nv_bfloat16 *Qhi, *Qlo, *Khi, *Klo, *Vhi, *Vlo, *Ahi, *Alo, *Whi, *Wlo;
    cudaGetSymbolAddress((void**)&Qhi, g_Qhi);
    cudaGetSymbolAddress((void**)&Qlo, g_Qlo);
    cudaGetSymbolAddress((void**)&Khi, g_Khi);
    cudaGetSymbolAddress((void**)&Klo, g_Klo);
    cudaGetSymbolAddress((void**)&Vhi, g_Vhi);
    cudaGetSymbolAddress((void**)&Vlo, g_Vlo);
    cudaGetSymbolAddress((void**)&Ahi, g_Ahi);
    cudaGetSymbolAddress((void**)&Alo, g_Alo);
    cudaGetSymbolAddress((void**)&Whi, g_Whi);
    cudaGetSymbolAddress((void**)&Wlo, g_Wlo);

    cudaFuncSetAttribute(flash_mma, cudaFuncAttributeMaxDynamicSharedMemorySize, FA_SMEM);

    const int nA = M_TOTAL * D_MODEL;
    const int nW = D_MODEL * D_MODEL;
    dim3 ggrid(D_MODEL / 128, M_TOTAL / 128);   // (6, 64)

    // Q projection -> split bf16 out
    split_bf16<<<nA / 1024, 256>>>(query, Ahi, Alo, nA);
    split_bf16<<<nW / 1024, 256>>>(Wq, Whi, Wlo, nW);
    gemm_mma<1><<<ggrid, 256>>>(Ahi, Alo, Whi, Wlo, bq, nullptr, Qhi, Qlo);
    // K projection
    split_bf16<<<nA / 1024, 256>>>(key, Ahi, Alo, nA);
    split_bf16<<<nW / 1024, 256>>>(Wk, Whi, Wlo, nW);
    gemm_mma<1><<<ggrid, 256>>>(Ahi, Alo, Whi, Wlo, bk, nullptr, Khi, Klo);
    // V projection
    split_bf16<<<nA / 1024, 256>>>(value, Ahi, Alo, nA);
    split_bf16<<<nW / 1024, 256>>>(Wv, Whi, Wlo, nW);
    gemm_mma<1><<<ggrid, 256>>>(Ahi, Alo, Whi, Wlo, bv, nullptr, Vhi, Vlo);

    // attention -> writes (Ahi, Alo) for the final projection
    dim3 agrid(SEQ / 128, NUM_HEADS, BATCH);     // (16, 12, 4)
    flash_mma<<<agrid, 256, FA_SMEM>>>(Qhi, Qlo, Khi, Klo, Vhi, Vlo, Ahi, Alo);

    // output projection -> fp32 out
    split_bf16<<<nW / 1024, 256>>>(Wo, Whi, Wlo, nW);
    gemm_mma<0><<<ggrid, 256>>>(Ahi, Alo, Whi, Wlo, bo, out, nullptr, nullptr);
}

// round 5
// speedup vs baseline: 3.0721x; 1.2688x over previous
#include <cuda_runtime.h>
#include <cuda_bf16.h>
#include <cstdint>

#define D_MODEL   768
#define NUM_HEADS 12
#define D_K       64
#define BATCH     4
#define SEQ       2048
#define M_TOTAL   (BATCH * SEQ)   // 8192

// ---------------- scratch (no allocations allowed) ----------------
__device__ __nv_bfloat16 g_Qhi[M_TOTAL * D_MODEL];
__device__ __nv_bfloat16 g_Qlo[M_TOTAL * D_MODEL];
__device__ __nv_bfloat16 g_Khi[M_TOTAL * D_MODEL];
__device__ __nv_bfloat16 g_Klo[M_TOTAL * D_MODEL];
__device__ __nv_bfloat16 g_Vhi[M_TOTAL * D_MODEL];
__device__ __nv_bfloat16 g_Vlo[M_TOTAL * D_MODEL];
__device__ __nv_bfloat16 g_Ahi[M_TOTAL * D_MODEL];
__device__ __nv_bfloat16 g_Alo[M_TOTAL * D_MODEL];
__device__ __nv_bfloat16 g_Whi[D_MODEL * D_MODEL];
__device__ __nv_bfloat16 g_Wlo[D_MODEL * D_MODEL];

// ---------------- helpers ----------------
__device__ __forceinline__ uint32_t smem_u32(const void* p) {
    uint32_t a;
    asm("{ .reg .u64 t; cvta.to.shared.u64 t, %1; cvt.u32.u64 %0, t; }" : "=r"(a) : "l"(p));
    return a;
}
__device__ __forceinline__ void mma16816(float* c, const uint32_t* a, const uint32_t* b) {
    asm volatile(
        "mma.sync.aligned.m16n8k16.row.col.f32.bf16.bf16.f32 "
        "{%0,%1,%2,%3}, {%4,%5,%6,%7}, {%8,%9}, {%0,%1,%2,%3};"
        : "+f"(c[0]), "+f"(c[1]), "+f"(c[2]), "+f"(c[3])
        : "r"(a[0]), "r"(a[1]), "r"(a[2]), "r"(a[3]), "r"(b[0]), "r"(b[1]));
}
#define LDSM4(r, addr) \
    asm volatile("ldmatrix.sync.aligned.m8n8.x4.shared.b16 {%0,%1,%2,%3}, [%4];" \
        : "=r"((r)[0]), "=r"((r)[1]), "=r"((r)[2]), "=r"((r)[3]) : "r"(addr))
#define LDSM4T(r, addr) \
    asm volatile("ldmatrix.sync.aligned.m8n8.x4.trans.shared.b16 {%0,%1,%2,%3}, [%4];" \
        : "=r"((r)[0]), "=r"((r)[1]), "=r"((r)[2]), "=r"((r)[3]) : "r"(addr))
__device__ __forceinline__ void cp16(uint32_t dst, const void* src) {
    asm volatile("cp.async.cg.shared.global [%0], [%1], 16;" :: "r"(dst), "l"(src) : "memory");
}
#define CP_COMMIT asm volatile("cp.async.commit_group;" ::: "memory")
#define CP_WAIT1  asm volatile("cp.async.wait_group 1;" ::: "memory")
#define CP_WAIT0  asm volatile("cp.async.wait_group 0;" ::: "memory")

__device__ __forceinline__ uint32_t pack_bf16(float x, float y) {
    __nv_bfloat16 bx = __float2bfloat16(x), by = __float2bfloat16(y);
    uint16_t ux = *(uint16_t*)&bx, uy = *(uint16_t*)&by;
    return (uint32_t)ux | ((uint32_t)uy << 16);
}
__device__ __forceinline__ void split_pack2(float x, float y, uint32_t& hi, uint32_t& lo) {
    __nv_bfloat16 hx = __float2bfloat16(x), hy = __float2bfloat16(y);
    float rx = x - __bfloat162float(hx);
    float ry = y - __bfloat162float(hy);
    uint16_t a = *(uint16_t*)&hx, b = *(uint16_t*)&hy;
    hi = (uint32_t)a | ((uint32_t)b << 16);
    lo = pack_bf16(rx, ry);
}

// =================================================================
// fp32 -> (hi, lo) bf16 split
// =================================================================
__global__ __launch_bounds__(256) void split_bf16(
    const float* __restrict__ x, __nv_bfloat16* __restrict__ hi,
    __nv_bfloat16* __restrict__ lo, int n)
{
    int i = (blockIdx.x * 256 + threadIdx.x) * 4;
    if (i >= n) return;
    float4 v = *(const float4*)(x + i);
    float f[4] = {v.x, v.y, v.z, v.w};
    unsigned short h[4], l[4];
#pragma unroll
    for (int u = 0; u < 4; ++u) {
        __nv_bfloat16 hh = __float2bfloat16(f[u]);
        __nv_bfloat16 ll = __float2bfloat16(f[u] - __bfloat162float(hh));
        h[u] = *(unsigned short*)&hh;
        l[u] = *(unsigned short*)&ll;
    }
    *(ushort4*)((unsigned short*)hi + i) = make_ushort4(h[0], h[1], h[2], h[3]);
    *(ushort4*)((unsigned short*)lo + i) = make_ushort4(l[0], l[1], l[2], l[3]);
}

// =================================================================
// Tensor-core GEMM: C = A @ W^T + bias, 3-term bf16 split.
// cp.async double-buffered, ldmatrix fragment loads.
// MODE 0: fp32 C out.  MODE 1: split bf16 (Chi, Clo) out.
// =================================================================
#define KC  32
#define NC  (D_MODEL / KC)
#define PAD 40
#define ST_MAT (128 * PAD)
#define STAGE_ELEMS (4 * ST_MAT)
#define GEMM_SMEM (2 * STAGE_ELEMS * 2)   // 81920 B

template<int MODE>
__global__ __launch_bounds__(256, 2) void gemm_mma(
    const __nv_bfloat16* __restrict__ Ahi, const __nv_bfloat16* __restrict__ Alo,
    const __nv_bfloat16* __restrict__ Whi, const __nv_bfloat16* __restrict__ Wlo,
    const float* __restrict__ bias, float* __restrict__ C,
    __nv_bfloat16* __restrict__ Chi, __nv_bfloat16* __restrict__ Clo)
{
    extern __shared__ __nv_bfloat16 gsm[];
    const uint32_t sb = smem_u32(gsm);
    const int tid  = threadIdx.x;
    const int wid  = tid >> 5;
    const int lane = tid & 31;
    const int g    = lane >> 2;
    const int q    = lane & 3;
    const int warpM = wid & 3;
    const int warpN = wid >> 2;
    const int row0 = blockIdx.y * 128;
    const int col0 = blockIdx.x * 128;

    const __nv_bfloat16* gA[4] = {
        Ahi + (size_t)row0 * D_MODEL, Alo + (size_t)row0 * D_MODEL,
        Whi + (size_t)col0 * D_MODEL, Wlo + (size_t)col0 * D_MODEL };

    const int ldr = tid >> 2;          // load rows: ldr, ldr+64
    const int ldc = (tid & 3) * 8;

    // ldmatrix lane address offsets
    const int arow = (lane & 7) | (((lane >> 3) & 1) << 3);
    const int acol = (lane >> 4) << 3;
    const int brow = (lane & 7) | (((lane >> 4) & 1) << 3);
    const int bcol = ((lane >> 3) & 1) << 3;
    const uint32_t aoff = sb + (uint32_t)(((warpM * 32 + arow) * PAD + acol) * 2);
    const uint32_t woff = sb + (uint32_t)(((warpN * 64 + brow) * PAD + bcol) * 2);

    float acc[2][8][4];
#pragma unroll
    for (int i = 0; i < 2; ++i)
#pragma unroll
        for (int j = 0; j < 8; ++j)
#pragma unroll
            for (int u = 0; u < 4; ++u) acc[i][j][u] = 0.f;

    auto issue = [&](int c, int s) {
        const int k0 = c * KC;
        const uint32_t sbase = sb + (uint32_t)(s * STAGE_ELEMS * 2);
#pragma unroll
        for (int m = 0; m < 4; ++m)
#pragma unroll
            for (int p = 0; p < 2; ++p) {
                int r = ldr + p * 64;
                cp16(sbase + (uint32_t)((m * ST_MAT + r * PAD + ldc) * 2),
                     gA[m] + (size_t)r * D_MODEL + k0 + ldc);
            }
        CP_COMMIT;
    };

    issue(0, 0);
    for (int c = 0; c < NC; ++c) {
        const int s = c & 1;
        __syncthreads();                 // all warps done with buffer s^1
        if (c + 1 < NC) { issue(c + 1, s ^ 1); CP_WAIT1; } else { CP_WAIT0; }
        __syncthreads();                 // buffer s visible to all

        const uint32_t stg = (uint32_t)(s * STAGE_ELEMS * 2);
#pragma unroll
        for (int ks = 0; ks < 2; ++ks) {
            uint32_t a[2][2][4];
#pragma unroll
            for (int t = 0; t < 2; ++t)
#pragma unroll
                for (int mf = 0; mf < 2; ++mf)
                    LDSM4(a[t][mf], aoff + stg +
                          (uint32_t)((t * ST_MAT + mf * 16 * PAD + ks * 16) * 2));
#pragma unroll
            for (int nfp = 0; nfp < 4; ++nfp) {
                uint32_t bh[4], bl[4];
                LDSM4(bh, woff + stg + (uint32_t)((2 * ST_MAT + nfp * 16 * PAD + ks * 16) * 2));
                LDSM4(bl, woff + stg + (uint32_t)((3 * ST_MAT + nfp * 16 * PAD + ks * 16) * 2));
#pragma unroll
                for (int mf = 0; mf < 2; ++mf) {
                    mma16816(acc[mf][2 * nfp],     a[0][mf], &bh[0]);
                    mma16816(acc[mf][2 * nfp],     a[0][mf], &bl[0]);
                    mma16816(acc[mf][2 * nfp],     a[1][mf], &bh[0]);
                    mma16816(acc[mf][2 * nfp + 1], a[0][mf], &bh[2]);
                    mma16816(acc[mf][2 * nfp + 1], a[0][mf], &bl[2]);
                    mma16816(acc[mf][2 * nfp + 1], a[1][mf], &bh[2]);
                }
            }
        }
    }

#pragma unroll
    for (int mf = 0; mf < 2; ++mf) {
        const int row = row0 + warpM * 32 + mf * 16 + g;
#pragma unroll
        for (int nf = 0; nf < 8; ++nf) {
            const int col = col0 + warpN * 64 + nf * 8 + q * 2;
            float2 bv = *(const float2*)(bias + col);
            float v0 = acc[mf][nf][0] + bv.x, v1 = acc[mf][nf][1] + bv.y;
            float v2 = acc[mf][nf][2] + bv.x, v3 = acc[mf][nf][3] + bv.y;
            if (MODE == 0) {
                *(float2*)(C + (size_t)row * D_MODEL + col) = make_float2(v0, v1);
                *(float2*)(C + (size_t)(row + 8) * D_MODEL + col) = make_float2(v2, v3);
            } else {
                uint32_t h0, l0, h1, l1;
                split_pack2(v0, v1, h0, l0);
                split_pack2(v2, v3, h1, l1);
                *(uint32_t*)(Chi + (size_t)row * D_MODEL + col) = h0;
                *(uint32_t*)(Clo + (size_t)row * D_MODEL + col) = l0;
                *(uint32_t*)(Chi + (size_t)(row + 8) * D_MODEL + col) = h1;
                *(uint32_t*)(Clo + (size_t)(row + 8) * D_MODEL + col) = l1;
            }
        }
    }
}

// =================================================================
// Tensor-core flash attention: cp.async double-buffered KV,
// ldmatrix fragment loads, P in registers.
// =================================================================
#define FPAD 72
#define FQH 0
#define FQL (128 * FPAD)
#define FST(s) ((256 + (s) * 256) * FPAD)
#define FA_SMEM (768 * FPAD * 2)   // 110592 B

__global__ __launch_bounds__(256, 2) void flash_mma(
    const __nv_bfloat16* __restrict__ Qh_, const __nv_bfloat16* __restrict__ Ql_,
    const __nv_bfloat16* __restrict__ Kh_, const __nv_bfloat16* __restrict__ Kl_,
    const __nv_bfloat16* __restrict__ Vh_, const __nv_bfloat16* __restrict__ Vl_,
    __nv_bfloat16* __restrict__ Ohi, __nv_bfloat16* __restrict__ Olo)
{
    extern __shared__ __nv_bfloat16 sm[];
    const uint32_t sb = smem_u32(sm);
    const int tid = threadIdx.x, wid = tid >> 5, lane = tid & 31;
    const int g = lane >> 2, q4 = lane & 3;
    const int q0 = blockIdx.x * 128;
    const int h  = blockIdx.y;
    const int b  = blockIdx.z;
    const size_t base = (size_t)b * SEQ * D_MODEL + h * 64;

    // ---- Q tile (128 x 64, hi+lo), plain loads ----
#pragma unroll
    for (int p = 0; p < 4; ++p) {
        int s = p * 256 + tid;
        int r = s >> 3, c = (s & 7) * 8;
        const size_t ga = base + (size_t)(q0 + r) * D_MODEL + c;
        *(uint4*)&sm[FQH + r * FPAD + c] = *(const uint4*)(Qh_ + ga);
        *(uint4*)&sm[FQL + r * FPAD + c] = *(const uint4*)(Ql_ + ga);
    }

    // ldmatrix lane address offsets
    const int arow = (lane & 7) | (((lane >> 3) & 1) << 3);
    const int acol = (lane >> 4) << 3;
    const int brow = (lane & 7) | (((lane >> 4) & 1) << 3);
    const int bcol = ((lane >> 3) & 1) << 3;
    const uint32_t qoffH = sb + (uint32_t)((FQH + (wid * 16 + arow) * FPAD + acol) * 2);
    const uint32_t qoffL = sb + (uint32_t)((FQL + (wid * 16 + arow) * FPAD + acol) * 2);
    const uint32_t koff  = (uint32_t)((brow * FPAD + bcol) * 2);
    const int lrow = (lane & 7) + ((lane >> 3) & 1) * 8;
    const int lcol = (lane >> 4) << 3;
    const uint32_t voff = (uint32_t)((lrow * FPAD + lcol) * 2);

    const int ldr = tid >> 3;          // KV load rows: ldr, ldr+32
    const int ldc = (tid & 7) * 8;

    auto issueKV = [&](int t, int s) {
        const size_t gb = base + (size_t)(t * 64) * D_MODEL;
        const uint32_t sbase = sb + (uint32_t)(FST(s) * 2);
        const __nv_bfloat16* srcs[4] = { Kh_ + gb, Kl_ + gb, Vh_ + gb, Vl_ + gb };
#pragma unroll
        for (int m = 0; m < 4; ++m)
#pragma unroll
            for (int p = 0; p < 2; ++p) {
                int r = ldr + p * 32;
                cp16(sbase + (uint32_t)((m * 64 * FPAD + r * FPAD + ldc) * 2),
                     srcs[m] + (size_t)r * D_MODEL + ldc);
            }
        CP_COMMIT;
    };

    float m0 = -1e30f, m1 = -1e30f, l0 = 0.f, l1 = 0.f;
    float oacc[8][4];
#pragma unroll
    for (int j = 0; j < 8; ++j)
#pragma unroll
        for (int u = 0; u < 4; ++u) oacc[j][u] = 0.f;

    issueKV(0, 0);
    for (int t = 0; t < SEQ / 64; ++t) {
        const int s = t & 1;
        __syncthreads();                  // prev tile's reads complete
        if (t + 1 < SEQ / 64) { issueKV(t + 1, s ^ 1); CP_WAIT1; } else { CP_WAIT0; }
        __syncthreads();                  // tile t visible (also fences Q on t=0)

        const uint32_t kst = sb + (uint32_t)(FST(s) * 2);

        // ---- S = Q K^T ----
        float sc[8][4];
#pragma unroll
        for (int j = 0; j < 8; ++j)
#pragma unroll
            for (int u = 0; u < 4; ++u) sc[j][u] = 0.f;

#pragma unroll
        for (int kg = 0; kg < 4; ++kg) {
            uint32_t ah[4], al[4];
            LDSM4(ah, qoffH + kg * 32);
            LDSM4(al, qoffL + kg * 32);
#pragma unroll
            for (int nfp = 0; nfp < 4; ++nfp) {
                uint32_t bh[4], bl[4];
                LDSM4(bh, kst + koff + (uint32_t)(nfp * 16 * FPAD * 2) + kg * 32);
                LDSM4(bl, kst + koff + (uint32_t)((64 * FPAD + nfp * 16 * FPAD) * 2) + kg * 32);
                mma16816(sc[2 * nfp],     ah, &bh[0]);
                mma16816(sc[2 * nfp],     ah, &bl[0]);
                mma16816(sc[2 * nfp],     al, &bh[0]);
                mma16816(sc[2 * nfp + 1], ah, &bh[2]);
                mma16816(sc[2 * nfp + 1], ah, &bl[2]);
                mma16816(sc[2 * nfp + 1], al, &bh[2]);
            }
        }

        // ---- online softmax ----
        float t0 = -1e30f, t1 = -1e30f;
#pragma unroll
        for (int nf = 0; nf < 8; ++nf) {
#pragma unroll
            for (int u = 0; u < 4; ++u) sc[nf][u] *= 0.125f;
            t0 = fmaxf(t0, fmaxf(sc[nf][0], sc[nf][1]));
            t1 = fmaxf(t1, fmaxf(sc[nf][2], sc[nf][3]));
        }
        t0 = fmaxf(t0, __shfl_xor_sync(0xffffffffu, t0, 1));
        t0 = fmaxf(t0, __shfl_xor_sync(0xffffffffu, t0, 2));
        t1 = fmaxf(t1, __shfl_xor_sync(0xffffffffu, t1, 1));
        t1 = fmaxf(t1, __shfl_xor_sync(0xffffffffu, t1, 2));
        float mn0 = fmaxf(m0, t0), mn1 = fmaxf(m1, t1);
        float c0 = __expf(m0 - mn0), c1 = __expf(m1 - mn1);
        m0 = mn0; m1 = mn1;
        float rs0 = 0.f, rs1 = 0.f;
#pragma unroll
        for (int nf = 0; nf < 8; ++nf) {
            sc[nf][0] = __expf(sc[nf][0] - m0);
            sc[nf][1] = __expf(sc[nf][1] - m0);
            sc[nf][2] = __expf(sc[nf][2] - m1);
            sc[nf][3] = __expf(sc[nf][3] - m1);
            rs0 += sc[nf][0] + sc[nf][1];
            rs1 += sc[nf][2] + sc[nf][3];
        }
        rs0 += __shfl_xor_sync(0xffffffffu, rs0, 1);
        rs0 += __shfl_xor_sync(0xffffffffu, rs0, 2);
        rs1 += __shfl_xor_sync(0xffffffffu, rs1, 1);
        rs1 += __shfl_xor_sync(0xffffffffu, rs1, 2);
        l0 = l0 * c0 + rs0;
        l1 = l1 * c1 + rs1;
#pragma unroll
        for (int nf = 0; nf < 8; ++nf) {
            oacc[nf][0] *= c0; oacc[nf][1] *= c0;
            oacc[nf][2] *= c1; oacc[nf][3] *= c1;
        }

        // ---- O += P V ----
        const uint32_t vH = kst + (uint32_t)(128 * FPAD * 2);
        const uint32_t vL = kst + (uint32_t)(192 * FPAD * 2);
#pragma unroll
        for (int kg = 0; kg < 4; ++kg) {
            uint32_t pah[4], pal[4];
            split_pack2(sc[2 * kg][0],     sc[2 * kg][1],     pah[0], pal[0]);
            split_pack2(sc[2 * kg][2],     sc[2 * kg][3],     pah[1], pal[1]);
            split_pack2(sc[2 * kg + 1][0], sc[2 * kg + 1][1], pah[2], pal[2]);
            split_pack2(sc[2 * kg + 1][2], sc[2 * kg + 1][3], pah[3], pal[3]);
            const uint32_t rowoff = voff + (uint32_t)(kg * 16 * FPAD * 2);
#pragma unroll
            for (int nf2 = 0; nf2 < 4; ++nf2) {
                uint32_t bh[4], bl[4];
                LDSM4T(bh, vH + rowoff + nf2 * 32);
                LDSM4T(bl, vL + rowoff + nf2 * 32);
                mma16816(oacc[2 * nf2],     pah, &bh[0]);
                mma16816(oacc[2 * nf2],     pah, &bl[0]);
                mma16816(oacc[2 * nf2],     pal, &bh[0]);
                mma16816(oacc[2 * nf2 + 1], pah, &bh[2]);
                mma16816(oacc[2 * nf2 + 1], pah, &bl[2]);
                mma16816(oacc[2 * nf2 + 1], pal, &bh[2]);
            }
        }
    }

    // ---- epilogue ----
    const float inv0 = 1.f / l0, inv1 = 1.f / l1;
    const int row0 = q0 + wid * 16 + g;
#pragma unroll
    for (int nf = 0; nf < 8; ++nf) {
        const int col = h * 64 + nf * 8 + q4 * 2;
        float v0 = oacc[nf][0] * inv0, v1 = oacc[nf][1] * inv0;
        float v2 = oacc[nf][2] * inv1, v3 = oacc[nf][3] * inv1;
        uint32_t h0, lo0, h1, lo1;
        split_pack2(v0, v1, h0, lo0);
        split_pack2(v2, v3, h1, lo1);
        *(uint32_t*)(Ohi + (size_t)(b * SEQ + row0) * D_MODEL + col) = h0;
        *(uint32_t*)(Olo + (size_t)(b * SEQ + row0) * D_MODEL + col) = lo0;
        *(uint32_t*)(Ohi + (size_t)(b * SEQ + row0 + 8) * D_MODEL + col) = h1;
        *(uint32_t*)(Olo + (size_t)(b * SEQ + row0 + 8) * D_MODEL + col) = lo1;
    }
}

// =================================================================
// Launch
// =================================================================
extern "C" void kernel_launch(void* const* d_in, const int* in_sizes, int n_in,
                              void* d_out, int out_size)
{
    const float* query = (const float*)d_in[0];
    const float* key   = (const float*)d_in[1];
    const float* value = (const float*)d_in[2];
    const float* Wq = (const float*)d_in[3];
    const float* bq = (const float*)d_in[4];
    const float* Wk = (const float*)d_in[5];
    const float* bk = (const float*)d_in[6];
    const float* Wv = (const float*)d_in[7];
    const float* bv = (const float*)d_in[8];
    const float* Wo = (const float*)d_in[9];
    const float* bo = (const float*)d_in[10];
    float* out = (float*)d_out;

    __nv_bfloat16 *Qhi, *Qlo, *Khi, *Klo, *Vhi, *Vlo, *Ahi, *Alo, *Whi, *Wlo;
    cudaGetSymbolAddress((void**)&Qhi, g_Qhi);
    cudaGetSymbolAddress((void**)&Qlo, g_Qlo);
    cudaGetSymbolAddress((void**)&Khi, g_Khi);
    cudaGetSymbolAddress((void**)&Klo, g_Klo);
    cudaGetSymbolAddress((void**)&Vhi, g_Vhi);
    cudaGetSymbolAddress((void**)&Vlo, g_Vlo);
    cudaGetSymbolAddress((void**)&Ahi, g_Ahi);
    cudaGetSymbolAddress((void**)&Alo, g_Alo);
    cudaGetSymbolAddress((void**)&Whi, g_Whi);
    cudaGetSymbolAddress((void**)&Wlo, g_Wlo);

    static bool attr_done = false;
    if (!attr_done) {
        cudaFuncSetAttribute(gemm_mma<0>, cudaFuncAttributeMaxDynamicSharedMemorySize, GEMM_SMEM);
        cudaFuncSetAttribute(gemm_mma<1>, cudaFuncAttributeMaxDynamicSharedMemorySize, GEMM_SMEM);
        cudaFuncSetAttribute(flash_mma, cudaFuncAttributeMaxDynamicSharedMemorySize, FA_SMEM);
        attr_done = true;
    }

    const int nA = M_TOTAL * D_MODEL;
    const int nW = D_MODEL * D_MODEL;
    dim3 ggrid(D_MODEL / 128, M_TOTAL / 128);   // (6, 64)

    // Q projection -> split bf16 out
    split_bf16<<<nA / 1024, 256>>>(query, Ahi, Alo, nA);
    split_bf16<<<nW / 1024, 256>>>(Wq, Whi, Wlo, nW);
    gemm_mma<1><<<ggrid, 256, GEMM_SMEM>>>(Ahi, Alo, Whi, Wlo, bq, nullptr, Qhi, Qlo);
    // K projection
    split_bf16<<<nA / 1024, 256>>>(key, Ahi, Alo, nA);
    split_bf16<<<nW / 1024, 256>>>(Wk, Whi, Wlo, nW);
    gemm_mma<1><<<ggrid, 256, GEMM_SMEM>>>(Ahi, Alo, Whi, Wlo, bk, nullptr, Khi, Klo);
    // V projection
    split_bf16<<<nA / 1024, 256>>>(value, Ahi, Alo, nA);
    split_bf16<<<nW / 1024, 256>>>(Wv, Whi, Wlo, nW);
    gemm_mma<1><<<ggrid, 256, GEMM_SMEM>>>(Ahi, Alo, Whi, Wlo, bv, nullptr, Vhi, Vlo);

    // attention -> writes (Ahi, Alo) for the final projection
    dim3 agrid(SEQ / 128, NUM_HEADS, BATCH);     // (16, 12, 4)
    flash_mma<<<agrid, 256, FA_SMEM>>>(Qhi, Qlo, Khi, Klo, Vhi, Vlo, Ahi, Alo);

    // output projection -> fp32 out
    split_bf16<<<nW / 1024, 256>>>(Wo, Whi, Wlo, nW);
    gemm_mma<0><<<ggrid, 256, GEMM_SMEM>>>(Ahi, Alo, Whi, Wlo, bo, out, nullptr, nullptr);
}

// round 6
// speedup vs baseline: 4.4366x; 1.4441x over previous
#include <cuda_runtime.h>
#include <cuda_bf16.h>
#include <cuda_fp16.h>
#include <cstdint>

#define D_MODEL   768
#define NUM_HEADS 12
#define D_K       64
#define BATCH     4
#define SEQ       2048
#define M_TOTAL   (BATCH * SEQ)   // 8192

// ---------------- scratch (no allocations allowed) ----------------
__device__ __half g_Qf[M_TOTAL * D_MODEL];
__device__ __half g_Kf[M_TOTAL * D_MODEL];
__device__ __half g_Vf[M_TOTAL * D_MODEL];
__device__ __nv_bfloat16 g_Ahi[M_TOTAL * D_MODEL];
__device__ __nv_bfloat16 g_Alo[M_TOTAL * D_MODEL];
__device__ __nv_bfloat16 g_Whi[D_MODEL * D_MODEL];
__device__ __nv_bfloat16 g_Wlo[D_MODEL * D_MODEL];

// ---------------- helpers ----------------
__device__ __forceinline__ uint32_t smem_u32(const void* p) {
    uint32_t a;
    asm("{ .reg .u64 t; cvta.to.shared.u64 t, %1; cvt.u32.u64 %0, t; }" : "=r"(a) : "l"(p));
    return a;
}
__device__ __forceinline__ void mma16816(float* c, const uint32_t* a, const uint32_t* b) {
    asm volatile(
        "mma.sync.aligned.m16n8k16.row.col.f32.bf16.bf16.f32 "
        "{%0,%1,%2,%3}, {%4,%5,%6,%7}, {%8,%9}, {%0,%1,%2,%3};"
        : "+f"(c[0]), "+f"(c[1]), "+f"(c[2]), "+f"(c[3])
        : "r"(a[0]), "r"(a[1]), "r"(a[2]), "r"(a[3]), "r"(b[0]), "r"(b[1]));
}
__device__ __forceinline__ void mma16816h(float* c, const uint32_t* a, const uint32_t* b) {
    asm volatile(
        "mma.sync.aligned.m16n8k16.row.col.f32.f16.f16.f32 "
        "{%0,%1,%2,%3}, {%4,%5,%6,%7}, {%8,%9}, {%0,%1,%2,%3};"
        : "+f"(c[0]), "+f"(c[1]), "+f"(c[2]), "+f"(c[3])
        : "r"(a[0]), "r"(a[1]), "r"(a[2]), "r"(a[3]), "r"(b[0]), "r"(b[1]));
}
#define LDSM4(r, addr) \
    asm volatile("ldmatrix.sync.aligned.m8n8.x4.shared.b16 {%0,%1,%2,%3}, [%4];" \
        : "=r"((r)[0]), "=r"((r)[1]), "=r"((r)[2]), "=r"((r)[3]) : "r"(addr))
#define LDSM4T(r, addr) \
    asm volatile("ldmatrix.sync.aligned.m8n8.x4.trans.shared.b16 {%0,%1,%2,%3}, [%4];" \
        : "=r"((r)[0]), "=r"((r)[1]), "=r"((r)[2]), "=r"((r)[3]) : "r"(addr))
__device__ __forceinline__ void cp16(uint32_t dst, const void* src) {
    asm volatile("cp.async.cg.shared.global [%0], [%1], 16;" :: "r"(dst), "l"(src) : "memory");
}
#define CP_COMMIT asm volatile("cp.async.commit_group;" ::: "memory")
#define CP_WAIT1  asm volatile("cp.async.wait_group 1;" ::: "memory")
#define CP_WAIT0  asm volatile("cp.async.wait_group 0;" ::: "memory")

__device__ __forceinline__ uint32_t pack_bf16(float x, float y) {
    __nv_bfloat16 bx = __float2bfloat16(x), by = __float2bfloat16(y);
    uint16_t ux = *(uint16_t*)&bx, uy = *(uint16_t*)&by;
    return (uint32_t)ux | ((uint32_t)uy << 16);
}
__device__ __forceinline__ uint32_t pack_h(float x, float y) {
    __half2 h = __floats2half2_rn(x, y);
    return *(uint32_t*)&h;
}
__device__ __forceinline__ void split_pack2(float x, float y, uint32_t& hi, uint32_t& lo) {
    __nv_bfloat16 hx = __float2bfloat16(x), hy = __float2bfloat16(y);
    float rx = x - __bfloat162float(hx);
    float ry = y - __bfloat162float(hy);
    uint16_t a = *(uint16_t*)&hx, b = *(uint16_t*)&hy;
    hi = (uint32_t)a | ((uint32_t)b << 16);
    lo = pack_bf16(rx, ry);
}

// =================================================================
// fp32 -> (hi, lo) bf16 split
// =================================================================
__global__ __launch_bounds__(256) void split_bf16(
    const float* __restrict__ x, __nv_bfloat16* __restrict__ hi,
    __nv_bfloat16* __restrict__ lo, int n)
{
    int i = (blockIdx.x * 256 + threadIdx.x) * 4;
    if (i >= n) return;
    float4 v = *(const float4*)(x + i);
    float f[4] = {v.x, v.y, v.z, v.w};
    unsigned short h[4], l[4];
#pragma unroll
    for (int u = 0; u < 4; ++u) {
        __nv_bfloat16 hh = __float2bfloat16(f[u]);
        __nv_bfloat16 ll = __float2bfloat16(f[u] - __bfloat162float(hh));
        h[u] = *(unsigned short*)&hh;
        l[u] = *(unsigned short*)&ll;
    }
    *(ushort4*)((unsigned short*)hi + i) = make_ushort4(h[0], h[1], h[2], h[3]);
    *(ushort4*)((unsigned short*)lo + i) = make_ushort4(l[0], l[1], l[2], l[3]);
}

// =================================================================
// Tensor-core GEMM: C = A @ W^T + bias, 3-term bf16 split inputs.
// MODE 0: fp32 C.  MODE 2: fp16 C scaled (for attention Q/K/V).
// =================================================================
#define KC  32
#define NC  (D_MODEL / KC)
#define PAD 40
#define ST_MAT (128 * PAD)
#define STAGE_ELEMS (4 * ST_MAT)
#define GEMM_SMEM (2 * STAGE_ELEMS * 2)   // 81920 B

template<int MODE>
__global__ __launch_bounds__(256, 2) void gemm_mma(
    const __nv_bfloat16* __restrict__ Ahi, const __nv_bfloat16* __restrict__ Alo,
    const __nv_bfloat16* __restrict__ Whi, const __nv_bfloat16* __restrict__ Wlo,
    const float* __restrict__ bias, float* __restrict__ C,
    __half* __restrict__ Cf, float scale)
{
    extern __shared__ __nv_bfloat16 gsm[];
    const uint32_t sb = smem_u32(gsm);
    const int tid  = threadIdx.x;
    const int wid  = tid >> 5;
    const int lane = tid & 31;
    const int g    = lane >> 2;
    const int q    = lane & 3;
    const int warpM = wid & 3;
    const int warpN = wid >> 2;
    const int row0 = blockIdx.y * 128;
    const int col0 = blockIdx.x * 128;

    const __nv_bfloat16* gA[4] = {
        Ahi + (size_t)row0 * D_MODEL, Alo + (size_t)row0 * D_MODEL,
        Whi + (size_t)col0 * D_MODEL, Wlo + (size_t)col0 * D_MODEL };

    const int ldr = tid >> 2;
    const int ldc = (tid & 3) * 8;

    const int arow = (lane & 7) | (((lane >> 3) & 1) << 3);
    const int acol = (lane >> 4) << 3;
    const int brow = (lane & 7) | (((lane >> 4) & 1) << 3);
    const int bcol = ((lane >> 3) & 1) << 3;
    const uint32_t aoff = sb + (uint32_t)(((warpM * 32 + arow) * PAD + acol) * 2);
    const uint32_t woff = sb + (uint32_t)(((warpN * 64 + brow) * PAD + bcol) * 2);

    float acc[2][8][4];
#pragma unroll
    for (int i = 0; i < 2; ++i)
#pragma unroll
        for (int j = 0; j < 8; ++j)
#pragma unroll
            for (int u = 0; u < 4; ++u) acc[i][j][u] = 0.f;

    auto issue = [&](int c, int s) {
        const int k0 = c * KC;
        const uint32_t sbase = sb + (uint32_t)(s * STAGE_ELEMS * 2);
#pragma unroll
        for (int m = 0; m < 4; ++m)
#pragma unroll
            for (int p = 0; p < 2; ++p) {
                int r = ldr + p * 64;
                cp16(sbase + (uint32_t)((m * ST_MAT + r * PAD + ldc) * 2),
                     gA[m] + (size_t)r * D_MODEL + k0 + ldc);
            }
        CP_COMMIT;
    };

    issue(0, 0);
    for (int c = 0; c < NC; ++c) {
        const int s = c & 1;
        __syncthreads();
        if (c + 1 < NC) { issue(c + 1, s ^ 1); CP_WAIT1; } else { CP_WAIT0; }
        __syncthreads();

        const uint32_t stg = (uint32_t)(s * STAGE_ELEMS * 2);
#pragma unroll
        for (int ks = 0; ks < 2; ++ks) {
            uint32_t a[2][2][4];
#pragma unroll
            for (int t = 0; t < 2; ++t)
#pragma unroll
                for (int mf = 0; mf < 2; ++mf)
                    LDSM4(a[t][mf], aoff + stg +
                          (uint32_t)((t * ST_MAT + mf * 16 * PAD + ks * 16) * 2));
#pragma unroll
            for (int nfp = 0; nfp < 4; ++nfp) {
                uint32_t bh[4], bl[4];
                LDSM4(bh, woff + stg + (uint32_t)((2 * ST_MAT + nfp * 16 * PAD + ks * 16) * 2));
                LDSM4(bl, woff + stg + (uint32_t)((3 * ST_MAT + nfp * 16 * PAD + ks * 16) * 2));
#pragma unroll
                for (int mf = 0; mf < 2; ++mf) {
                    mma16816(acc[mf][2 * nfp],     a[0][mf], &bh[0]);
                    mma16816(acc[mf][2 * nfp],     a[0][mf], &bl[0]);
                    mma16816(acc[mf][2 * nfp],     a[1][mf], &bh[0]);
                    mma16816(acc[mf][2 * nfp + 1], a[0][mf], &bh[2]);
                    mma16816(acc[mf][2 * nfp + 1], a[0][mf], &bl[2]);
                    mma16816(acc[mf][2 * nfp + 1], a[1][mf], &bh[2]);
                }
            }
        }
    }

#pragma unroll
    for (int mf = 0; mf < 2; ++mf) {
        const int row = row0 + warpM * 32 + mf * 16 + g;
#pragma unroll
        for (int nf = 0; nf < 8; ++nf) {
            const int col = col0 + warpN * 64 + nf * 8 + q * 2;
            float2 bv = *(const float2*)(bias + col);
            float v0 = acc[mf][nf][0] + bv.x, v1 = acc[mf][nf][1] + bv.y;
            float v2 = acc[mf][nf][2] + bv.x, v3 = acc[mf][nf][3] + bv.y;
            if (MODE == 0) {
                *(float2*)(C + (size_t)row * D_MODEL + col) = make_float2(v0, v1);
                *(float2*)(C + (size_t)(row + 8) * D_MODEL + col) = make_float2(v2, v3);
            } else {
                *(uint32_t*)(Cf + (size_t)row * D_MODEL + col) = pack_h(v0 * scale, v1 * scale);
                *(uint32_t*)(Cf + (size_t)(row + 8) * D_MODEL + col) = pack_h(v2 * scale, v3 * scale);
            }
        }
    }
}

// =================================================================
// Tensor-core flash attention — single fp16 (S and PV), cp.async
// double-buffered KV, ldmatrix fragments, P in registers.
// Q pre-scaled by 1/8 in projection epilogue.
// =================================================================
#define FPAD 72
#define FST(s) ((128 + (s) * 128) * FPAD)
#define FA_SMEM (384 * FPAD * 2)   // 55296 B

__global__ __launch_bounds__(256, 2) void flash_mma(
    const __half* __restrict__ Qf, const __half* __restrict__ Kf,
    const __half* __restrict__ Vf,
    __nv_bfloat16* __restrict__ Ohi, __nv_bfloat16* __restrict__ Olo)
{
    extern __shared__ __half sm[];
    const uint32_t sb = smem_u32(sm);
    const int tid = threadIdx.x, wid = tid >> 5, lane = tid & 31;
    const int g = lane >> 2, q4 = lane & 3;
    const int q0 = blockIdx.x * 128;
    const int h  = blockIdx.y;
    const int b  = blockIdx.z;
    const size_t base = (size_t)b * SEQ * D_MODEL + h * 64;

    // ---- Q tile (128 x 64 fp16) ----
#pragma unroll
    for (int p = 0; p < 4; ++p) {
        int s = p * 256 + tid;
        int r = s >> 3, c = (s & 7) * 8;
        *(uint4*)&sm[r * FPAD + c] = *(const uint4*)(Qf + base + (size_t)(q0 + r) * D_MODEL + c);
    }

    const int arow = (lane & 7) | (((lane >> 3) & 1) << 3);
    const int acol = (lane >> 4) << 3;
    const int brow = (lane & 7) | (((lane >> 4) & 1) << 3);
    const int bcol = ((lane >> 3) & 1) << 3;
    const uint32_t qoff = sb + (uint32_t)(((wid * 16 + arow) * FPAD + acol) * 2);
    const uint32_t koff = (uint32_t)((brow * FPAD + bcol) * 2);
    const int lrow = (lane & 7) + ((lane >> 3) & 1) * 8;
    const int lcol = (lane >> 4) << 3;
    const uint32_t voff = (uint32_t)((lrow * FPAD + lcol) * 2);

    const int ldr = tid >> 3;
    const int ldc = (tid & 7) * 8;

    auto issueKV = [&](int t, int s) {
        const size_t gb = base + (size_t)(t * 64) * D_MODEL;
        const uint32_t sbase = sb + (uint32_t)(FST(s) * 2);
        const __half* srcs[2] = { Kf + gb, Vf + gb };
#pragma unroll
        for (int m = 0; m < 2; ++m)
#pragma unroll
            for (int p = 0; p < 2; ++p) {
                int r = ldr + p * 32;
                cp16(sbase + (uint32_t)((m * 64 * FPAD + r * FPAD + ldc) * 2),
                     srcs[m] + (size_t)r * D_MODEL + ldc);
            }
        CP_COMMIT;
    };

    float m0 = -1e30f, m1 = -1e30f, l0 = 0.f, l1 = 0.f;
    float oacc[8][4];
#pragma unroll
    for (int j = 0; j < 8; ++j)
#pragma unroll
        for (int u = 0; u < 4; ++u) oacc[j][u] = 0.f;

    issueKV(0, 0);
    for (int t = 0; t < SEQ / 64; ++t) {
        const int s = t & 1;
        __syncthreads();
        if (t + 1 < SEQ / 64) { issueKV(t + 1, s ^ 1); CP_WAIT1; } else { CP_WAIT0; }
        __syncthreads();

        const uint32_t kst = sb + (uint32_t)(FST(s) * 2);

        // ---- S = Q K^T (fp16 single) ----
        float sc[8][4];
#pragma unroll
        for (int j = 0; j < 8; ++j)
#pragma unroll
            for (int u = 0; u < 4; ++u) sc[j][u] = 0.f;

#pragma unroll
        for (int kg = 0; kg < 4; ++kg) {
            uint32_t af[4];
            LDSM4(af, qoff + kg * 32);
#pragma unroll
            for (int nfp = 0; nfp < 4; ++nfp) {
                uint32_t bf[4];
                LDSM4(bf, kst + koff + (uint32_t)(nfp * 16 * FPAD * 2) + kg * 32);
                mma16816h(sc[2 * nfp],     af, &bf[0]);
                mma16816h(sc[2 * nfp + 1], af, &bf[2]);
            }
        }

        // ---- online softmax (Q pre-scaled, no extra multiply) ----
        float t0 = -1e30f, t1 = -1e30f;
#pragma unroll
        for (int nf = 0; nf < 8; ++nf) {
            t0 = fmaxf(t0, fmaxf(sc[nf][0], sc[nf][1]));
            t1 = fmaxf(t1, fmaxf(sc[nf][2], sc[nf][3]));
        }
        t0 = fmaxf(t0, __shfl_xor_sync(0xffffffffu, t0, 1));
        t0 = fmaxf(t0, __shfl_xor_sync(0xffffffffu, t0, 2));
        t1 = fmaxf(t1, __shfl_xor_sync(0xffffffffu, t1, 1));
        t1 = fmaxf(t1, __shfl_xor_sync(0xffffffffu, t1, 2));
        float mn0 = fmaxf(m0, t0), mn1 = fmaxf(m1, t1);
        float c0 = __expf(m0 - mn0), c1 = __expf(m1 - mn1);
        m0 = mn0; m1 = mn1;
        float rs0 = 0.f, rs1 = 0.f;
#pragma unroll
        for (int nf = 0; nf < 8; ++nf) {
            sc[nf][0] = __expf(sc[nf][0] - m0);
            sc[nf][1] = __expf(sc[nf][1] - m0);
            sc[nf][2] = __expf(sc[nf][2] - m1);
            sc[nf][3] = __expf(sc[nf][3] - m1);
            rs0 += sc[nf][0] + sc[nf][1];
            rs1 += sc[nf][2] + sc[nf][3];
        }
        rs0 += __shfl_xor_sync(0xffffffffu, rs0, 1);
        rs0 += __shfl_xor_sync(0xffffffffu, rs0, 2);
        rs1 += __shfl_xor_sync(0xffffffffu, rs1, 1);
        rs1 += __shfl_xor_sync(0xffffffffu, rs1, 2);
        l0 = l0 * c0 + rs0;
        l1 = l1 * c1 + rs1;
#pragma unroll
        for (int nf = 0; nf < 8; ++nf) {
            oacc[nf][0] *= c0; oacc[nf][1] *= c0;
            oacc[nf][2] *= c1; oacc[nf][3] *= c1;
        }

        // ---- O += P V (fp16 single) ----
        const uint32_t vb = kst + (uint32_t)(64 * FPAD * 2);
#pragma unroll
        for (int kg = 0; kg < 4; ++kg) {
            uint32_t pa[4];
            pa[0] = pack_h(sc[2 * kg][0],     sc[2 * kg][1]);
            pa[1] = pack_h(sc[2 * kg][2],     sc[2 * kg][3]);
            pa[2] = pack_h(sc[2 * kg + 1][0], sc[2 * kg + 1][1]);
            pa[3] = pack_h(sc[2 * kg + 1][2], sc[2 * kg + 1][3]);
            const uint32_t rowoff = voff + (uint32_t)(kg * 16 * FPAD * 2);
#pragma unroll
            for (int nf2 = 0; nf2 < 4; ++nf2) {
                uint32_t bv[4];
                LDSM4T(bv, vb + rowoff + nf2 * 32);
                mma16816h(oacc[2 * nf2],     pa, &bv[0]);
                mma16816h(oacc[2 * nf2 + 1], pa, &bv[2]);
            }
        }
    }

    // ---- epilogue: normalize, split to (hi,lo) bf16 for final GEMM ----
    const float inv0 = 1.f / l0, inv1 = 1.f / l1;
    const int row0 = q0 + wid * 16 + g;
#pragma unroll
    for (int nf = 0; nf < 8; ++nf) {
        const int col = h * 64 + nf * 8 + q4 * 2;
        float v0 = oacc[nf][0] * inv0, v1 = oacc[nf][1] * inv0;
        float v2 = oacc[nf][2] * inv1, v3 = oacc[nf][3] * inv1;
        uint32_t h0, lo0, h1, lo1;
        split_pack2(v0, v1, h0, lo0);
        split_pack2(v2, v3, h1, lo1);
        *(uint32_t*)(Ohi + (size_t)(b * SEQ + row0) * D_MODEL + col) = h0;
        *(uint32_t*)(Olo + (size_t)(b * SEQ + row0) * D_MODEL + col) = lo0;
        *(uint32_t*)(Ohi + (size_t)(b * SEQ + row0 + 8) * D_MODEL + col) = h1;
        *(uint32_t*)(Olo + (size_t)(b * SEQ + row0 + 8) * D_MODEL + col) = lo1;
    }
}

// =================================================================
// Launch
// =================================================================
extern "C" void kernel_launch(void* const* d_in, const int* in_sizes, int n_in,
                              void* d_out, int out_size)
{
    const float* query = (const float*)d_in[0];
    const float* key   = (const float*)d_in[1];
    const float* value = (const float*)d_in[2];
    const float* Wq = (const float*)d_in[3];
    const float* bq = (const float*)d_in[4];
    const float* Wk = (const float*)d_in[5];
    const float* bk = (const float*)d_in[6];
    const float* Wv = (const float*)d_in[7];
    const float* bv = (const float*)d_in[8];
    const float* Wo = (const float*)d_in[9];
    const float* bo = (const float*)d_in[10];
    float* out = (float*)d_out;

    __half *Qf, *Kf, *Vf;
    __nv_bfloat16 *Ahi, *Alo, *Whi, *Wlo;
    cudaGetSymbolAddress((void**)&Qf, g_Qf);
    cudaGetSymbolAddress((void**)&Kf, g_Kf);
    cudaGetSymbolAddress((void**)&Vf, g_Vf);
    cudaGetSymbolAddress((void**)&Ahi, g_Ahi);
    cudaGetSymbolAddress((void**)&Alo, g_Alo);
    cudaGetSymbolAddress((void**)&Whi, g_Whi);
    cudaGetSymbolAddress((void**)&Wlo, g_Wlo);

    static bool attr_done = false;
    if (!attr_done) {
        cudaFuncSetAttribute(gemm_mma<0>, cudaFuncAttributeMaxDynamicSharedMemorySize, GEMM_SMEM);
        cudaFuncSetAttribute(gemm_mma<2>, cudaFuncAttributeMaxDynamicSharedMemorySize, GEMM_SMEM);
        cudaFuncSetAttribute(flash_mma, cudaFuncAttributeMaxDynamicSharedMemorySize, FA_SMEM);
        attr_done = true;
    }

    const int nA = M_TOTAL * D_MODEL;
    const int nW = D_MODEL * D_MODEL;
    dim3 ggrid(D_MODEL / 128, M_TOTAL / 128);   // (6, 64)

    // Q projection -> fp16, pre-scaled by 1/sqrt(Dk)
    split_bf16<<<nA / 1024, 256>>>(query, Ahi, Alo, nA);
    split_bf16<<<nW / 1024, 256>>>(Wq, Whi, Wlo, nW);
    gemm_mma<2><<<ggrid, 256, GEMM_SMEM>>>(Ahi, Alo, Whi, Wlo, bq, nullptr, Qf, 0.125f);
    // K projection -> fp16
    split_bf16<<<nA / 1024, 256>>>(key, Ahi, Alo, nA);
    split_bf16<<<nW / 1024, 256>>>(Wk, Whi, Wlo, nW);
    gemm_mma<2><<<ggrid, 256, GEMM_SMEM>>>(Ahi, Alo, Whi, Wlo, bk, nullptr, Kf, 1.0f);
    // V projection -> fp16
    split_bf16<<<nA / 1024, 256>>>(value, Ahi, Alo, nA);
    split_bf16<<<nW / 1024, 256>>>(Wv, Whi, Wlo, nW);
    gemm_mma<2><<<ggrid, 256, GEMM_SMEM>>>(Ahi, Alo, Whi, Wlo, bv, nullptr, Vf, 1.0f);

    // attention -> writes (Ahi, Alo) for the final projection
    dim3 agrid(SEQ / 128, NUM_HEADS, BATCH);     // (16, 12, 4)
    flash_mma<<<agrid, 256, FA_SMEM>>>(Qf, Kf, Vf, Ahi, Alo);

    // output projection -> fp32 out
    split_bf16<<<nW / 1024, 256>>>(Wo, Whi, Wlo, nW);
    gemm_mma<0><<<ggrid, 256, GEMM_SMEM>>>(Ahi, Alo, Whi, Wlo, bo, out, nullptr, 1.0f);
}

// round 7
// speedup vs baseline: 5.8822x; 1.3258x over previous
#include <cuda_runtime.h>
#include <cuda_bf16.h>
#include <cuda_fp16.h>
#include <cstdint>

#define D_MODEL   768
#define NUM_HEADS 12
#define D_K       64
#define BATCH     4
#define SEQ       2048
#define M_TOTAL   (BATCH * SEQ)   // 8192

// ---------------- scratch (no allocations allowed) ----------------
__device__ __half g_Qf[M_TOTAL * D_MODEL];
__device__ __half g_Kf[M_TOTAL * D_MODEL];
__device__ __half g_Vf[M_TOTAL * D_MODEL];
__device__ __half g_Af[M_TOTAL * D_MODEL];
__device__ __half g_Wf[D_MODEL * D_MODEL];
__device__ __nv_bfloat16 g_Ahi[M_TOTAL * D_MODEL];
__device__ __nv_bfloat16 g_Alo[M_TOTAL * D_MODEL];
__device__ __nv_bfloat16 g_Whi[D_MODEL * D_MODEL];
__device__ __nv_bfloat16 g_Wlo[D_MODEL * D_MODEL];

// ---------------- helpers ----------------
__device__ __forceinline__ uint32_t smem_u32(const void* p) {
    uint32_t a;
    asm("{ .reg .u64 t; cvta.to.shared.u64 t, %1; cvt.u32.u64 %0, t; }" : "=r"(a) : "l"(p));
    return a;
}
__device__ __forceinline__ void mma16816(float* c, const uint32_t* a, const uint32_t* b) {
    asm volatile(
        "mma.sync.aligned.m16n8k16.row.col.f32.bf16.bf16.f32 "
        "{%0,%1,%2,%3}, {%4,%5,%6,%7}, {%8,%9}, {%0,%1,%2,%3};"
        : "+f"(c[0]), "+f"(c[1]), "+f"(c[2]), "+f"(c[3])
        : "r"(a[0]), "r"(a[1]), "r"(a[2]), "r"(a[3]), "r"(b[0]), "r"(b[1]));
}
__device__ __forceinline__ void mma16816h(float* c, const uint32_t* a, const uint32_t* b) {
    asm volatile(
        "mma.sync.aligned.m16n8k16.row.col.f32.f16.f16.f32 "
        "{%0,%1,%2,%3}, {%4,%5,%6,%7}, {%8,%9}, {%0,%1,%2,%3};"
        : "+f"(c[0]), "+f"(c[1]), "+f"(c[2]), "+f"(c[3])
        : "r"(a[0]), "r"(a[1]), "r"(a[2]), "r"(a[3]), "r"(b[0]), "r"(b[1]));
}
#define LDSM4(r, addr) \
    asm volatile("ldmatrix.sync.aligned.m8n8.x4.shared.b16 {%0,%1,%2,%3}, [%4];" \
        : "=r"((r)[0]), "=r"((r)[1]), "=r"((r)[2]), "=r"((r)[3]) : "r"(addr))
#define LDSM4T(r, addr) \
    asm volatile("ldmatrix.sync.aligned.m8n8.x4.trans.shared.b16 {%0,%1,%2,%3}, [%4];" \
        : "=r"((r)[0]), "=r"((r)[1]), "=r"((r)[2]), "=r"((r)[3]) : "r"(addr))
__device__ __forceinline__ void cp16(uint32_t dst, const void* src) {
    asm volatile("cp.async.cg.shared.global [%0], [%1], 16;" :: "r"(dst), "l"(src) : "memory");
}
#define CP_COMMIT asm volatile("cp.async.commit_group;" ::: "memory")
#define CP_WAIT1  asm volatile("cp.async.wait_group 1;" ::: "memory")
#define CP_WAIT0  asm volatile("cp.async.wait_group 0;" ::: "memory")

__device__ __forceinline__ uint32_t pack_bf16(float x, float y) {
    __nv_bfloat16 bx = __float2bfloat16(x), by = __float2bfloat16(y);
    uint16_t ux = *(uint16_t*)&bx, uy = *(uint16_t*)&by;
    return (uint32_t)ux | ((uint32_t)uy << 16);
}
__device__ __forceinline__ uint32_t pack_h(float x, float y) {
    __half2 h = __floats2half2_rn(x, y);
    return *(uint32_t*)&h;
}
__device__ __forceinline__ void split_pack2(float x, float y, uint32_t& hi, uint32_t& lo) {
    __nv_bfloat16 hx = __float2bfloat16(x), hy = __float2bfloat16(y);
    float rx = x - __bfloat162float(hx);
    float ry = y - __bfloat162float(hy);
    uint16_t a = *(uint16_t*)&hx, b = *(uint16_t*)&hy;
    hi = (uint32_t)a | ((uint32_t)b << 16);
    lo = pack_bf16(rx, ry);
}

// =================================================================
// conversion kernels
// =================================================================
__global__ __launch_bounds__(256) void split_bf16(
    const float* __restrict__ x, __nv_bfloat16* __restrict__ hi,
    __nv_bfloat16* __restrict__ lo, int n)
{
    int i = (blockIdx.x * 256 + threadIdx.x) * 4;
    if (i >= n) return;
    float4 v = *(const float4*)(x + i);
    float f[4] = {v.x, v.y, v.z, v.w};
    unsigned short h[4], l[4];
#pragma unroll
    for (int u = 0; u < 4; ++u) {
        __nv_bfloat16 hh = __float2bfloat16(f[u]);
        __nv_bfloat16 ll = __float2bfloat16(f[u] - __bfloat162float(hh));
        h[u] = *(unsigned short*)&hh;
        l[u] = *(unsigned short*)&ll;
    }
    *(ushort4*)((unsigned short*)hi + i) = make_ushort4(h[0], h[1], h[2], h[3]);
    *(ushort4*)((unsigned short*)lo + i) = make_ushort4(l[0], l[1], l[2], l[3]);
}

__global__ __launch_bounds__(256) void tofp16(
    const float* __restrict__ x, __half* __restrict__ y, int n)
{
    int i = (blockIdx.x * 256 + threadIdx.x) * 4;
    if (i >= n) return;
    float4 v = *(const float4*)(x + i);
    uint32_t a = pack_h(v.x, v.y), b = pack_h(v.z, v.w);
    *(uint2*)(y + i) = make_uint2(a, b);
}

// =================================================================
// fp16 single-term GEMM: Cf = (A @ W^T + bias) * scale   (fp16 out)
// 128x128 CTA tile, KC=32, cp.async double buffer, ldmatrix.
// =================================================================
#define KC  32
#define NC  (D_MODEL / KC)
#define PAD 40
#define HST_MAT (128 * PAD)
#define HSTAGE  (2 * HST_MAT)
#define GEMMH_SMEM (2 * HSTAGE * 2)   // 40960 B

__global__ __launch_bounds__(256, 2) void gemm_h(
    const __half* __restrict__ Af, const __half* __restrict__ Wf,
    const float* __restrict__ bias, __half* __restrict__ Cf, float scale)
{
    extern __shared__ __half hsm[];
    const uint32_t sb = smem_u32(hsm);
    const int tid  = threadIdx.x;
    const int wid  = tid >> 5;
    const int lane = tid & 31;
    const int g    = lane >> 2;
    const int q    = lane & 3;
    const int warpM = wid & 3;
    const int warpN = wid >> 2;
    const int row0 = blockIdx.y * 128;
    const int col0 = blockIdx.x * 128;

    const __half* gA[2] = { Af + (size_t)row0 * D_MODEL, Wf + (size_t)col0 * D_MODEL };
    const int ldr = tid >> 2;
    const int ldc = (tid & 3) * 8;

    const int arow = (lane & 7) | (((lane >> 3) & 1) << 3);
    const int acol = (lane >> 4) << 3;
    const int brow = (lane & 7) | (((lane >> 4) & 1) << 3);
    const int bcol = ((lane >> 3) & 1) << 3;
    const uint32_t aoff = sb + (uint32_t)(((warpM * 32 + arow) * PAD + acol) * 2);
    const uint32_t woff = sb + (uint32_t)((HST_MAT + (warpN * 64 + brow) * PAD + bcol) * 2);

    float acc[2][8][4];
#pragma unroll
    for (int i = 0; i < 2; ++i)
#pragma unroll
        for (int j = 0; j < 8; ++j)
#pragma unroll
            for (int u = 0; u < 4; ++u) acc[i][j][u] = 0.f;

    auto issue = [&](int c, int s) {
        const int k0 = c * KC;
        const uint32_t sbase = sb + (uint32_t)(s * HSTAGE * 2);
#pragma unroll
        for (int m = 0; m < 2; ++m)
#pragma unroll
            for (int p = 0; p < 2; ++p) {
                int r = ldr + p * 64;
                cp16(sbase + (uint32_t)((m * HST_MAT + r * PAD + ldc) * 2),
                     gA[m] + (size_t)r * D_MODEL + k0 + ldc);
            }
        CP_COMMIT;
    };

    issue(0, 0);
    for (int c = 0; c < NC; ++c) {
        const int s = c & 1;
        __syncthreads();
        if (c + 1 < NC) { issue(c + 1, s ^ 1); CP_WAIT1; } else { CP_WAIT0; }
        __syncthreads();

        const uint32_t stg = (uint32_t)(s * HSTAGE * 2);
#pragma unroll
        for (int ks = 0; ks < 2; ++ks) {
            uint32_t a[2][4];
#pragma unroll
            for (int mf = 0; mf < 2; ++mf)
                LDSM4(a[mf], aoff + stg + (uint32_t)((mf * 16 * PAD + ks * 16) * 2));
#pragma unroll
            for (int nfp = 0; nfp < 4; ++nfp) {
                uint32_t bf[4];
                LDSM4(bf, woff + stg + (uint32_t)((nfp * 16 * PAD + ks * 16) * 2));
#pragma unroll
                for (int mf = 0; mf < 2; ++mf) {
                    mma16816h(acc[mf][2 * nfp],     a[mf], &bf[0]);
                    mma16816h(acc[mf][2 * nfp + 1], a[mf], &bf[2]);
                }
            }
        }
    }

#pragma unroll
    for (int mf = 0; mf < 2; ++mf) {
        const int row = row0 + warpM * 32 + mf * 16 + g;
#pragma unroll
        for (int nf = 0; nf < 8; ++nf) {
            const int col = col0 + warpN * 64 + nf * 8 + q * 2;
            float2 bv = *(const float2*)(bias + col);
            float v0 = acc[mf][nf][0] + bv.x, v1 = acc[mf][nf][1] + bv.y;
            float v2 = acc[mf][nf][2] + bv.x, v3 = acc[mf][nf][3] + bv.y;
            *(uint32_t*)(Cf + (size_t)row * D_MODEL + col) = pack_h(v0 * scale, v1 * scale);
            *(uint32_t*)(Cf + (size_t)(row + 8) * D_MODEL + col) = pack_h(v2 * scale, v3 * scale);
        }
    }
}

// =================================================================
// 3-term bf16-split GEMM (output projection): C = A @ W^T + bias (fp32)
// =================================================================
#define ST_MAT (128 * PAD)
#define STAGE_ELEMS (4 * ST_MAT)
#define GEMM_SMEM (2 * STAGE_ELEMS * 2)   // 81920 B

__global__ __launch_bounds__(256, 2) void gemm_mma(
    const __nv_bfloat16* __restrict__ Ahi, const __nv_bfloat16* __restrict__ Alo,
    const __nv_bfloat16* __restrict__ Whi, const __nv_bfloat16* __restrict__ Wlo,
    const float* __restrict__ bias, float* __restrict__ C)
{
    extern __shared__ __nv_bfloat16 gsm[];
    const uint32_t sb = smem_u32(gsm);
    const int tid  = threadIdx.x;
    const int wid  = tid >> 5;
    const int lane = tid & 31;
    const int g    = lane >> 2;
    const int q    = lane & 3;
    const int warpM = wid & 3;
    const int warpN = wid >> 2;
    const int row0 = blockIdx.y * 128;
    const int col0 = blockIdx.x * 128;

    const __nv_bfloat16* gA[4] = {
        Ahi + (size_t)row0 * D_MODEL, Alo + (size_t)row0 * D_MODEL,
        Whi + (size_t)col0 * D_MODEL, Wlo + (size_t)col0 * D_MODEL };

    const int ldr = tid >> 2;
    const int ldc = (tid & 3) * 8;

    const int arow = (lane & 7) | (((lane >> 3) & 1) << 3);
    const int acol = (lane >> 4) << 3;
    const int brow = (lane & 7) | (((lane >> 4) & 1) << 3);
    const int bcol = ((lane >> 3) & 1) << 3;
    const uint32_t aoff = sb + (uint32_t)(((warpM * 32 + arow) * PAD + acol) * 2);
    const uint32_t woff = sb + (uint32_t)(((warpN * 64 + brow) * PAD + bcol) * 2);

    float acc[2][8][4];
#pragma unroll
    for (int i = 0; i < 2; ++i)
#pragma unroll
        for (int j = 0; j < 8; ++j)
#pragma unroll
            for (int u = 0; u < 4; ++u) acc[i][j][u] = 0.f;

    auto issue = [&](int c, int s) {
        const int k0 = c * KC;
        const uint32_t sbase = sb + (uint32_t)(s * STAGE_ELEMS * 2);
#pragma unroll
        for (int m = 0; m < 4; ++m)
#pragma unroll
            for (int p = 0; p < 2; ++p) {
                int r = ldr + p * 64;
                cp16(sbase + (uint32_t)((m * ST_MAT + r * PAD + ldc) * 2),
                     gA[m] + (size_t)r * D_MODEL + k0 + ldc);
            }
        CP_COMMIT;
    };

    issue(0, 0);
    for (int c = 0; c < NC; ++c) {
        const int s = c & 1;
        __syncthreads();
        if (c + 1 < NC) { issue(c + 1, s ^ 1); CP_WAIT1; } else { CP_WAIT0; }
        __syncthreads();

        const uint32_t stg = (uint32_t)(s * STAGE_ELEMS * 2);
#pragma unroll
        for (int ks = 0; ks < 2; ++ks) {
            uint32_t a[2][2][4];
#pragma unroll
            for (int t = 0; t < 2; ++t)
#pragma unroll
                for (int mf = 0; mf < 2; ++mf)
                    LDSM4(a[t][mf], aoff + stg +
                          (uint32_t)((t * ST_MAT + mf * 16 * PAD + ks * 16) * 2));
#pragma unroll
            for (int nfp = 0; nfp < 4; ++nfp) {
                uint32_t bh[4], bl[4];
                LDSM4(bh, woff + stg + (uint32_t)((2 * ST_MAT + nfp * 16 * PAD + ks * 16) * 2));
                LDSM4(bl, woff + stg + (uint32_t)((3 * ST_MAT + nfp * 16 * PAD + ks * 16) * 2));
#pragma unroll
                for (int mf = 0; mf < 2; ++mf) {
                    mma16816(acc[mf][2 * nfp],     a[0][mf], &bh[0]);
                    mma16816(acc[mf][2 * nfp],     a[0][mf], &bl[0]);
                    mma16816(acc[mf][2 * nfp],     a[1][mf], &bh[0]);
                    mma16816(acc[mf][2 * nfp + 1], a[0][mf], &bh[2]);
                    mma16816(acc[mf][2 * nfp + 1], a[0][mf], &bl[2]);
                    mma16816(acc[mf][2 * nfp + 1], a[1][mf], &bh[2]);
                }
            }
        }
    }

#pragma unroll
    for (int mf = 0; mf < 2; ++mf) {
        const int row = row0 + warpM * 32 + mf * 16 + g;
#pragma unroll
        for (int nf = 0; nf < 8; ++nf) {
            const int col = col0 + warpN * 64 + nf * 8 + q * 2;
            float2 bv = *(const float2*)(bias + col);
            *(float2*)(C + (size_t)row * D_MODEL + col) =
                make_float2(acc[mf][nf][0] + bv.x, acc[mf][nf][1] + bv.y);
            *(float2*)(C + (size_t)(row + 8) * D_MODEL + col) =
                make_float2(acc[mf][nf][2] + bv.x, acc[mf][nf][3] + bv.y);
        }
    }
}

// =================================================================
// Tensor-core flash attention — fp16, cp.async double-buffered KV.
// =================================================================
#define FPAD 72
#define FST(s) ((128 + (s) * 128) * FPAD)
#define FA_SMEM (384 * FPAD * 2)   // 55296 B

__global__ __launch_bounds__(256, 2) void flash_mma(
    const __half* __restrict__ Qf, const __half* __restrict__ Kf,
    const __half* __restrict__ Vf,
    __nv_bfloat16* __restrict__ Ohi, __nv_bfloat16* __restrict__ Olo)
{
    extern __shared__ __half sm[];
    const uint32_t sb = smem_u32(sm);
    const int tid = threadIdx.x, wid = tid >> 5, lane = tid & 31;
    const int g = lane >> 2, q4 = lane & 3;
    const int q0 = blockIdx.x * 128;
    const int h  = blockIdx.y;
    const int b  = blockIdx.z;
    const size_t base = (size_t)b * SEQ * D_MODEL + h * 64;

#pragma unroll
    for (int p = 0; p < 4; ++p) {
        int s = p * 256 + tid;
        int r = s >> 3, c = (s & 7) * 8;
        *(uint4*)&sm[r * FPAD + c] = *(const uint4*)(Qf + base + (size_t)(q0 + r) * D_MODEL + c);
    }

    const int arow = (lane & 7) | (((lane >> 3) & 1) << 3);
    const int acol = (lane >> 4) << 3;
    const int brow = (lane & 7) | (((lane >> 4) & 1) << 3);
    const int bcol = ((lane >> 3) & 1) << 3;
    const uint32_t qoff = sb + (uint32_t)(((wid * 16 + arow) * FPAD + acol) * 2);
    const uint32_t koff = (uint32_t)((brow * FPAD + bcol) * 2);
    const int lrow = (lane & 7) + ((lane >> 3) & 1) * 8;
    const int lcol = (lane >> 4) << 3;
    const uint32_t voff = (uint32_t)((lrow * FPAD + lcol) * 2);

    const int ldr = tid >> 3;
    const int ldc = (tid & 7) * 8;

    auto issueKV = [&](int t, int s) {
        const size_t gb = base + (size_t)(t * 64) * D_MODEL;
        const uint32_t sbase = sb + (uint32_t)(FST(s) * 2);
        const __half* srcs[2] = { Kf + gb, Vf + gb };
#pragma unroll
        for (int m = 0; m < 2; ++m)
#pragma unroll
            for (int p = 0; p < 2; ++p) {
                int r = ldr + p * 32;
                cp16(sbase + (uint32_t)((m * 64 * FPAD + r * FPAD + ldc) * 2),
                     srcs[m] + (size_t)r * D_MODEL + ldc);
            }
        CP_COMMIT;
    };

    float m0 = -1e30f, m1 = -1e30f, l0 = 0.f, l1 = 0.f;
    float oacc[8][4];
#pragma unroll
    for (int j = 0; j < 8; ++j)
#pragma unroll
        for (int u = 0; u < 4; ++u) oacc[j][u] = 0.f;

    issueKV(0, 0);
    for (int t = 0; t < SEQ / 64; ++t) {
        const int s = t & 1;
        __syncthreads();
        if (t + 1 < SEQ / 64) { issueKV(t + 1, s ^ 1); CP_WAIT1; } else { CP_WAIT0; }
        __syncthreads();

        const uint32_t kst = sb + (uint32_t)(FST(s) * 2);

        float sc[8][4];
#pragma unroll
        for (int j = 0; j < 8; ++j)
#pragma unroll
            for (int u = 0; u < 4; ++u) sc[j][u] = 0.f;

#pragma unroll
        for (int kg = 0; kg < 4; ++kg) {
            uint32_t af[4];
            LDSM4(af, qoff + kg * 32);
#pragma unroll
            for (int nfp = 0; nfp < 4; ++nfp) {
                uint32_t bf[4];
                LDSM4(bf, kst + koff + (uint32_t)(nfp * 16 * FPAD * 2) + kg * 32);
                mma16816h(sc[2 * nfp],     af, &bf[0]);
                mma16816h(sc[2 * nfp + 1], af, &bf[2]);
            }
        }

        float t0 = -1e30f, t1 = -1e30f;
#pragma unroll
        for (int nf = 0; nf < 8; ++nf) {
            t0 = fmaxf(t0, fmaxf(sc[nf][0], sc[nf][1]));
            t1 = fmaxf(t1, fmaxf(sc[nf][2], sc[nf][3]));
        }
        t0 = fmaxf(t0, __shfl_xor_sync(0xffffffffu, t0, 1));
        t0 = fmaxf(t0, __shfl_xor_sync(0xffffffffu, t0, 2));
        t1 = fmaxf(t1, __shfl_xor_sync(0xffffffffu, t1, 1));
        t1 = fmaxf(t1, __shfl_xor_sync(0xffffffffu, t1, 2));
        float mn0 = fmaxf(m0, t0), mn1 = fmaxf(m1, t1);
        float c0 = __expf(m0 - mn0), c1 = __expf(m1 - mn1);
        m0 = mn0; m1 = mn1;
        float rs0 = 0.f, rs1 = 0.f;
#pragma unroll
        for (int nf = 0; nf < 8; ++nf) {
            sc[nf][0] = __expf(sc[nf][0] - m0);
            sc[nf][1] = __expf(sc[nf][1] - m0);
            sc[nf][2] = __expf(sc[nf][2] - m1);
            sc[nf][3] = __expf(sc[nf][3] - m1);
            rs0 += sc[nf][0] + sc[nf][1];
            rs1 += sc[nf][2] + sc[nf][3];
        }
        rs0 += __shfl_xor_sync(0xffffffffu, rs0, 1);
        rs0 += __shfl_xor_sync(0xffffffffu, rs0, 2);
        rs1 += __shfl_xor_sync(0xffffffffu, rs1, 1);
        rs1 += __shfl_xor_sync(0xffffffffu, rs1, 2);
        l0 = l0 * c0 + rs0;
        l1 = l1 * c1 + rs1;
#pragma unroll
        for (int nf = 0; nf < 8; ++nf) {
            oacc[nf][0] *= c0; oacc[nf][1] *= c0;
            oacc[nf][2] *= c1; oacc[nf][3] *= c1;
        }

        const uint32_t vb = kst + (uint32_t)(64 * FPAD * 2);
#pragma unroll
        for (int kg = 0; kg < 4; ++kg) {
            uint32_t pa[4];
            pa[0] = pack_h(sc[2 * kg][0],     sc[2 * kg][1]);
            pa[1] = pack_h(sc[2 * kg][2],     sc[2 * kg][3]);
            pa[2] = pack_h(sc[2 * kg + 1][0], sc[2 * kg + 1][1]);
            pa[3] = pack_h(sc[2 * kg + 1][2], sc[2 * kg + 1][3]);
            const uint32_t rowoff = voff + (uint32_t)(kg * 16 * FPAD * 2);
#pragma unroll
            for (int nf2 = 0; nf2 < 4; ++nf2) {
                uint32_t bv[4];
                LDSM4T(bv, vb + rowoff + nf2 * 32);
                mma16816h(oacc[2 * nf2],     pa, &bv[0]);
                mma16816h(oacc[2 * nf2 + 1], pa, &bv[2]);
            }
        }
    }

    const float inv0 = 1.f / l0, inv1 = 1.f / l1;
    const int row0 = q0 + wid * 16 + g;
#pragma unroll
    for (int nf = 0; nf < 8; ++nf) {
        const int col = h * 64 + nf * 8 + q4 * 2;
        float v0 = oacc[nf][0] * inv0, v1 = oacc[nf][1] * inv0;
        float v2 = oacc[nf][2] * inv1, v3 = oacc[nf][3] * inv1;
        uint32_t h0, lo0, h1, lo1;
        split_pack2(v0, v1, h0, lo0);
        split_pack2(v2, v3, h1, lo1);
        *(uint32_t*)(Ohi + (size_t)(b * SEQ + row0) * D_MODEL + col) = h0;
        *(uint32_t*)(Olo + (size_t)(b * SEQ + row0) * D_MODEL + col) = lo0;
        *(uint32_t*)(Ohi + (size_t)(b * SEQ + row0 + 8) * D_MODEL + col) = h1;
        *(uint32_t*)(Olo + (size_t)(b * SEQ + row0 + 8) * D_MODEL + col) = lo1;
    }
}

// =================================================================
// Launch
// =================================================================
extern "C" void kernel_launch(void* const* d_in, const int* in_sizes, int n_in,
                              void* d_out, int out_size)
{
    const float* query = (const float*)d_in[0];
    const float* key   = (const float*)d_in[1];
    const float* value = (const float*)d_in[2];
    const float* Wq = (const float*)d_in[3];
    const float* bq = (const float*)d_in[4];
    const float* Wk = (const float*)d_in[5];
    const float* bk = (const float*)d_in[6];
    const float* Wv = (const float*)d_in[7];
    const float* bv = (const float*)d_in[8];
    const float* Wo = (const float*)d_in[9];
    const float* bo = (const float*)d_in[10];
    float* out = (float*)d_out;

    __half *Qf, *Kf, *Vf, *Af, *Wf;
    __nv_bfloat16 *Ahi, *Alo, *Whi, *Wlo;
    cudaGetSymbolAddress((void**)&Qf, g_Qf);
    cudaGetSymbolAddress((void**)&Kf, g_Kf);
    cudaGetSymbolAddress((void**)&Vf, g_Vf);
    cudaGetSymbolAddress((void**)&Af, g_Af);
    cudaGetSymbolAddress((void**)&Wf, g_Wf);
    cudaGetSymbolAddress((void**)&Ahi, g_Ahi);
    cudaGetSymbolAddress((void**)&Alo, g_Alo);
    cudaGetSymbolAddress((void**)&Whi, g_Whi);
    cudaGetSymbolAddress((void**)&Wlo, g_Wlo);

    static bool attr_done = false;
    if (!attr_done) {
        cudaFuncSetAttribute(gemm_h, cudaFuncAttributeMaxDynamicSharedMemorySize, GEMMH_SMEM);
        cudaFuncSetAttribute(gemm_mma, cudaFuncAttributeMaxDynamicSharedMemorySize, GEMM_SMEM);
        cudaFuncSetAttribute(flash_mma, cudaFuncAttributeMaxDynamicSharedMemorySize, FA_SMEM);
        attr_done = true;
    }

    const int nA = M_TOTAL * D_MODEL;
    const int nW = D_MODEL * D_MODEL;
    dim3 ggrid(D_MODEL / 128, M_TOTAL / 128);   // (6, 64)

    // Q projection (fp16 single-term), pre-scaled by 1/sqrt(Dk)
    tofp16<<<nA / 1024, 256>>>(query, Af, nA);
    tofp16<<<nW / 1024, 256>>>(Wq, Wf, nW);
    gemm_h<<<ggrid, 256, GEMMH_SMEM>>>(Af, Wf, bq, Qf, 0.125f);
    // K projection
    tofp16<<<nA / 1024, 256>>>(key, Af, nA);
    tofp16<<<nW / 1024, 256>>>(Wk, Wf, nW);
    gemm_h<<<ggrid, 256, GEMMH_SMEM>>>(Af, Wf, bk, Kf, 1.0f);
    // V projection
    tofp16<<<nA / 1024, 256>>>(value, Af, nA);
    tofp16<<<nW / 1024, 256>>>(Wv, Wf, nW);
    gemm_h<<<ggrid, 256, GEMMH_SMEM>>>(Af, Wf, bv, Vf, 1.0f);

    // attention -> writes (Ahi, Alo) for the final projection
    dim3 agrid(SEQ / 128, NUM_HEADS, BATCH);     // (16, 12, 4)
    flash_mma<<<agrid, 256, FA_SMEM>>>(Qf, Kf, Vf, Ahi, Alo);

    // output projection (3-term bf16 split) -> fp32 out
    split_bf16<<<nW / 1024, 256>>>(Wo, Whi, Wlo, nW);
    gemm_mma<<<ggrid, 256, GEMM_SMEM>>>(Ahi, Alo, Whi, Wlo, bo, out);
}

// round 9
// speedup vs baseline: 6.4269x; 1.0926x over previous
#include <cuda_runtime.h>
#include <cuda_bf16.h>
#include <cuda_fp16.h>
#include <cstdint>

#define D_MODEL   768
#define NUM_HEADS 12
#define D_K       64
#define BATCH     4
#define SEQ       2048
#define M_TOTAL   (BATCH * SEQ)   // 8192

// ---------------- scratch (no allocations allowed) ----------------
__device__ __half g_Qf[M_TOTAL * D_MODEL];
__device__ __half g_Kf[M_TOTAL * D_MODEL];
__device__ __half g_Vf[M_TOTAL * D_MODEL];
__device__ __nv_bfloat16 g_Ahi[M_TOTAL * D_MODEL];
__device__ __nv_bfloat16 g_Alo[M_TOTAL * D_MODEL];
__device__ __nv_bfloat16 g_Whi[D_MODEL * D_MODEL];
__device__ __nv_bfloat16 g_Wlo[D_MODEL * D_MODEL];

// ---------------- helpers ----------------
__device__ __forceinline__ uint32_t smem_u32(const void* p) {
    uint32_t a;
    asm("{ .reg .u64 t; cvta.to.shared.u64 t, %1; cvt.u32.u64 %0, t; }" : "=r"(a) : "l"(p));
    return a;
}
__device__ __forceinline__ void mma16816(float* c, const uint32_t* a, const uint32_t* b) {
    asm volatile(
        "mma.sync.aligned.m16n8k16.row.col.f32.bf16.bf16.f32 "
        "{%0,%1,%2,%3}, {%4,%5,%6,%7}, {%8,%9}, {%0,%1,%2,%3};"
        : "+f"(c[0]), "+f"(c[1]), "+f"(c[2]), "+f"(c[3])
        : "r"(a[0]), "r"(a[1]), "r"(a[2]), "r"(a[3]), "r"(b[0]), "r"(b[1]));
}
__device__ __forceinline__ void mma16816h(float* c, const uint32_t* a, const uint32_t* b) {
    asm volatile(
        "mma.sync.aligned.m16n8k16.row.col.f32.f16.f16.f32 "
        "{%0,%1,%2,%3}, {%4,%5,%6,%7}, {%8,%9}, {%0,%1,%2,%3};"
        : "+f"(c[0]), "+f"(c[1]), "+f"(c[2]), "+f"(c[3])
        : "r"(a[0]), "r"(a[1]), "r"(a[2]), "r"(a[3]), "r"(b[0]), "r"(b[1]));
}
#define LDSM4(r, addr) \
    asm volatile("ldmatrix.sync.aligned.m8n8.x4.shared.b16 {%0,%1,%2,%3}, [%4];" \
        : "=r"((r)[0]), "=r"((r)[1]), "=r"((r)[2]), "=r"((r)[3]) : "r"(addr))
#define LDSM4T(r, addr) \
    asm volatile("ldmatrix.sync.aligned.m8n8.x4.trans.shared.b16 {%0,%1,%2,%3}, [%4];" \
        : "=r"((r)[0]), "=r"((r)[1]), "=r"((r)[2]), "=r"((r)[3]) : "r"(addr))
__device__ __forceinline__ void cp16(uint32_t dst, const void* src) {
    asm volatile("cp.async.cg.shared.global [%0], [%1], 16;" :: "r"(dst), "l"(src) : "memory");
}
#define CP_COMMIT asm volatile("cp.async.commit_group;" ::: "memory")
#define CP_WAIT1  asm volatile("cp.async.wait_group 1;" ::: "memory")
#define CP_WAIT0  asm volatile("cp.async.wait_group 0;" ::: "memory")

__device__ __forceinline__ uint32_t pack_bf16(float x, float y) {
    __nv_bfloat16 bx = __float2bfloat16(x), by = __float2bfloat16(y);
    uint16_t ux = *(uint16_t*)&bx, uy = *(uint16_t*)&by;
    return (uint32_t)ux | ((uint32_t)uy << 16);
}
__device__ __forceinline__ uint32_t pack_h(float x, float y) {
    __half2 h = __floats2half2_rn(x, y);
    return *(uint32_t*)&h;
}
__device__ __forceinline__ void split_pack2(float x, float y, uint32_t& hi, uint32_t& lo) {
    __nv_bfloat16 hx = __float2bfloat16(x), hy = __float2bfloat16(y);
    float rx = x - __bfloat162float(hx);
    float ry = y - __bfloat162float(hy);
    uint16_t a = *(uint16_t*)&hx, b = *(uint16_t*)&hy;
    hi = (uint32_t)a | ((uint32_t)b << 16);
    lo = pack_bf16(rx, ry);
}

// =================================================================
// fp32 -> (hi, lo) bf16 split (Wo only)
// =================================================================
__global__ __launch_bounds__(256) void split_bf16(
    const float* __restrict__ x, __nv_bfloat16* __restrict__ hi,
    __nv_bfloat16* __restrict__ lo, int n)
{
    int i = (blockIdx.x * 256 + threadIdx.x) * 4;
    if (i >= n) return;
    float4 v = *(const float4*)(x + i);
    float f[4] = {v.x, v.y, v.z, v.w};
    unsigned short h[4], l[4];
#pragma unroll
    for (int u = 0; u < 4; ++u) {
        __nv_bfloat16 hh = __float2bfloat16(f[u]);
        __nv_bfloat16 ll = __float2bfloat16(f[u] - __bfloat162float(hh));
        h[u] = *(unsigned short*)&hh;
        l[u] = *(unsigned short*)&ll;
    }
    *(ushort4*)((unsigned short*)hi + i) = make_ushort4(h[0], h[1], h[2], h[3]);
    *(ushort4*)((unsigned short*)lo + i) = make_ushort4(l[0], l[1], l[2], l[3]);
}

// =================================================================
// Fused QKV projection: reads fp32 A/W, converts to fp16 in-register,
// fp16 tensor-core GEMM, fp16 out (Q pre-scaled by 1/8).
// grid.z in {0,1,2} selects (query,Wq)->Qf, (key,Wk)->Kf, (value,Wv)->Vf.
// Load coverage per matrix per chunk: 128 rows x 32 cols;
// thread slots: lr = tid>>3 in [0,32), lc = (tid&7)*4; r = lr + p*32.
// =================================================================
#define KC  32
#define NC  (D_MODEL / KC)
#define PAD 40
#define HST_MAT (128 * PAD)

__global__ __launch_bounds__(256, 2) void gemm_qkv(
    const float* __restrict__ q_, const float* __restrict__ k_, const float* __restrict__ v_,
    const float* __restrict__ Wq, const float* __restrict__ Wk, const float* __restrict__ Wv,
    const float* __restrict__ bq, const float* __restrict__ bk, const float* __restrict__ bv,
    __half* __restrict__ Qf, __half* __restrict__ Kf, __half* __restrict__ Vf)
{
    __shared__ __half st[2 * HST_MAT];   // A tile, W tile (fp16, 20 KB)

    const int z = blockIdx.z;
    const float* A    = (z == 0) ? q_ : (z == 1) ? k_ : v_;
    const float* W    = (z == 0) ? Wq : (z == 1) ? Wk : Wv;
    const float* bias = (z == 0) ? bq : (z == 1) ? bk : bv;
    __half* Cf        = (z == 0) ? Qf : (z == 1) ? Kf : Vf;
    const float scale = (z == 0) ? 0.125f : 1.0f;

    const uint32_t sb = smem_u32(st);
    const int tid  = threadIdx.x;
    const int wid  = tid >> 5;
    const int lane = tid & 31;
    const int g    = lane >> 2;
    const int q    = lane & 3;
    const int warpM = wid & 3;
    const int warpN = wid >> 2;
    const int row0 = blockIdx.y * 128;
    const int col0 = blockIdx.x * 128;

    const float* gA = A + (size_t)row0 * D_MODEL;
    const float* gW = W + (size_t)col0 * D_MODEL;

    // load slots: 4 per matrix; rows lr+p*32 (0..127), cols lc..lc+3 (0..31)
    const int lr = tid >> 3;          // 0..31
    const int lc = (tid & 7) * 4;     // 0,4,...,28

    const int arow = (lane & 7) | (((lane >> 3) & 1) << 3);
    const int acol = (lane >> 4) << 3;
    const int brow = (lane & 7) | (((lane >> 4) & 1) << 3);
    const int bcol = ((lane >> 3) & 1) << 3;
    const uint32_t aoff = sb + (uint32_t)(((warpM * 32 + arow) * PAD + acol) * 2);
    const uint32_t woff = sb + (uint32_t)((HST_MAT + (warpN * 64 + brow) * PAD + bcol) * 2);

    float acc[2][8][4];
#pragma unroll
    for (int i = 0; i < 2; ++i)
#pragma unroll
        for (int j = 0; j < 8; ++j)
#pragma unroll
            for (int u = 0; u < 4; ++u) acc[i][j][u] = 0.f;

    float4 pre[2][4];
#pragma unroll
    for (int p = 0; p < 4; ++p) {
        const int r = lr + p * 32;
        pre[0][p] = *(const float4*)(gA + (size_t)r * D_MODEL + lc);
        pre[1][p] = *(const float4*)(gW + (size_t)r * D_MODEL + lc);
    }

    for (int ch = 0; ch < NC; ++ch) {
        if (ch) __syncthreads();      // prior chunk's compute done
#pragma unroll
        for (int m = 0; m < 2; ++m)
#pragma unroll
            for (int p = 0; p < 4; ++p) {
                const int r = lr + p * 32;
                float4 v4 = pre[m][p];
                *(uint2*)&st[m * HST_MAT + r * PAD + lc] =
                    make_uint2(pack_h(v4.x, v4.y), pack_h(v4.z, v4.w));
            }
        if (ch + 1 < NC) {
            const int k0 = (ch + 1) * KC;
#pragma unroll
            for (int p = 0; p < 4; ++p) {
                const int r = lr + p * 32;
                pre[0][p] = *(const float4*)(gA + (size_t)r * D_MODEL + k0 + lc);
                pre[1][p] = *(const float4*)(gW + (size_t)r * D_MODEL + k0 + lc);
            }
        }
        __syncthreads();

#pragma unroll
        for (int ks = 0; ks < 2; ++ks) {
            uint32_t a[2][4];
#pragma unroll
            for (int mf = 0; mf < 2; ++mf)
                LDSM4(a[mf], aoff + (uint32_t)((mf * 16 * PAD + ks * 16) * 2));
#pragma unroll
            for (int nfp = 0; nfp < 4; ++nfp) {
                uint32_t bf[4];
                LDSM4(bf, woff + (uint32_t)((nfp * 16 * PAD + ks * 16) * 2));
#pragma unroll
                for (int mf = 0; mf < 2; ++mf) {
                    mma16816h(acc[mf][2 * nfp],     a[mf], &bf[0]);
                    mma16816h(acc[mf][2 * nfp + 1], a[mf], &bf[2]);
                }
            }
        }
    }

#pragma unroll
    for (int mf = 0; mf < 2; ++mf) {
        const int row = row0 + warpM * 32 + mf * 16 + g;
#pragma unroll
        for (int nf = 0; nf < 8; ++nf) {
            const int col = col0 + warpN * 64 + nf * 8 + q * 2;
            float2 bv = *(const float2*)(bias + col);
            float v0 = acc[mf][nf][0] + bv.x, v1 = acc[mf][nf][1] + bv.y;
            float v2 = acc[mf][nf][2] + bv.x, v3 = acc[mf][nf][3] + bv.y;
            *(uint32_t*)(Cf + (size_t)row * D_MODEL + col) = pack_h(v0 * scale, v1 * scale);
            *(uint32_t*)(Cf + (size_t)(row + 8) * D_MODEL + col) = pack_h(v2 * scale, v3 * scale);
        }
    }
}

// =================================================================
// 3-term bf16-split GEMM (output projection): C = A @ W^T + bias (fp32)
// =================================================================
#define ST_MAT (128 * PAD)
#define STAGE_ELEMS (4 * ST_MAT)
#define GEMM_SMEM (2 * STAGE_ELEMS * 2)   // 81920 B

__global__ __launch_bounds__(256, 2) void gemm_mma(
    const __nv_bfloat16* __restrict__ Ahi, const __nv_bfloat16* __restrict__ Alo,
    const __nv_bfloat16* __restrict__ Whi, const __nv_bfloat16* __restrict__ Wlo,
    const float* __restrict__ bias, float* __restrict__ C)
{
    extern __shared__ __nv_bfloat16 gsm[];
    const uint32_t sb = smem_u32(gsm);
    const int tid  = threadIdx.x;
    const int wid  = tid >> 5;
    const int lane = tid & 31;
    const int g    = lane >> 2;
    const int q    = lane & 3;
    const int warpM = wid & 3;
    const int warpN = wid >> 2;
    const int row0 = blockIdx.y * 128;
    const int col0 = blockIdx.x * 128;

    const __nv_bfloat16* gA[4] = {
        Ahi + (size_t)row0 * D_MODEL, Alo + (size_t)row0 * D_MODEL,
        Whi + (size_t)col0 * D_MODEL, Wlo + (size_t)col0 * D_MODEL };

    const int ldr = tid >> 2;
    const int ldc = (tid & 3) * 8;

    const int arow = (lane & 7) | (((lane >> 3) & 1) << 3);
    const int acol = (lane >> 4) << 3;
    const int brow = (lane & 7) | (((lane >> 4) & 1) << 3);
    const int bcol = ((lane >> 3) & 1) << 3;
    const uint32_t aoff = sb + (uint32_t)(((warpM * 32 + arow) * PAD + acol) * 2);
    const uint32_t woff = sb + (uint32_t)(((warpN * 64 + brow) * PAD + bcol) * 2);

    float acc[2][8][4];
#pragma unroll
    for (int i = 0; i < 2; ++i)
#pragma unroll
        for (int j = 0; j < 8; ++j)
#pragma unroll
            for (int u = 0; u < 4; ++u) acc[i][j][u] = 0.f;

    auto issue = [&](int c, int s) {
        const int k0 = c * KC;
        const uint32_t sbase = sb + (uint32_t)(s * STAGE_ELEMS * 2);
#pragma unroll
        for (int m = 0; m < 4; ++m)
#pragma unroll
            for (int p = 0; p < 2; ++p) {
                int r = ldr + p * 64;
                cp16(sbase + (uint32_t)((m * ST_MAT + r * PAD + ldc) * 2),
                     gA[m] + (size_t)r * D_MODEL + k0 + ldc);
            }
        CP_COMMIT;
    };

    issue(0, 0);
    for (int c = 0; c < NC; ++c) {
        const int s = c & 1;
        __syncthreads();
        if (c + 1 < NC) { issue(c + 1, s ^ 1); CP_WAIT1; } else { CP_WAIT0; }
        __syncthreads();

        const uint32_t stg = (uint32_t)(s * STAGE_ELEMS * 2);
#pragma unroll
        for (int ks = 0; ks < 2; ++ks) {
            uint32_t a[2][2][4];
#pragma unroll
            for (int t = 0; t < 2; ++t)
#pragma unroll
                for (int mf = 0; mf < 2; ++mf)
                    LDSM4(a[t][mf], aoff + stg +
                          (uint32_t)((t * ST_MAT + mf * 16 * PAD + ks * 16) * 2));
#pragma unroll
            for (int nfp = 0; nfp < 4; ++nfp) {
                uint32_t bh[4], bl[4];
                LDSM4(bh, woff + stg + (uint32_t)((2 * ST_MAT + nfp * 16 * PAD + ks * 16) * 2));
                LDSM4(bl, woff + stg + (uint32_t)((3 * ST_MAT + nfp * 16 * PAD + ks * 16) * 2));
#pragma unroll
                for (int mf = 0; mf < 2; ++mf) {
                    mma16816(acc[mf][2 * nfp],     a[0][mf], &bh[0]);
                    mma16816(acc[mf][2 * nfp],     a[0][mf], &bl[0]);
                    mma16816(acc[mf][2 * nfp],     a[1][mf], &bh[0]);
                    mma16816(acc[mf][2 * nfp + 1], a[0][mf], &bh[2]);
                    mma16816(acc[mf][2 * nfp + 1], a[0][mf], &bl[2]);
                    mma16816(acc[mf][2 * nfp + 1], a[1][mf], &bh[2]);
                }
            }
        }
    }

#pragma unroll
    for (int mf = 0; mf < 2; ++mf) {
        const int row = row0 + warpM * 32 + mf * 16 + g;
#pragma unroll
        for (int nf = 0; nf < 8; ++nf) {
            const int col = col0 + warpN * 64 + nf * 8 + q * 2;
            float2 bv = *(const float2*)(bias + col);
            *(float2*)(C + (size_t)row * D_MODEL + col) =
                make_float2(acc[mf][nf][0] + bv.x, acc[mf][nf][1] + bv.y);
            *(float2*)(C + (size_t)(row + 8) * D_MODEL + col) =
                make_float2(acc[mf][nf][2] + bv.x, acc[mf][nf][3] + bv.y);
        }
    }
}

// =================================================================
// Tensor-core flash attention — fp16, cp.async double-buffered KV.
// =================================================================
#define FPAD 72
#define FST(s) ((128 + (s) * 128) * FPAD)
#define FA_SMEM (384 * FPAD * 2)   // 55296 B

__global__ __launch_bounds__(256, 2) void flash_mma(
    const __half* __restrict__ Qf, const __half* __restrict__ Kf,
    const __half* __restrict__ Vf,
    __nv_bfloat16* __restrict__ Ohi, __nv_bfloat16* __restrict__ Olo)
{
    extern __shared__ __half sm[];
    const uint32_t sb = smem_u32(sm);
    const int tid = threadIdx.x, wid = tid >> 5, lane = tid & 31;
    const int g = lane >> 2, q4 = lane & 3;
    const int q0 = blockIdx.x * 128;
    const int h  = blockIdx.y;
    const int b  = blockIdx.z;
    const size_t base = (size_t)b * SEQ * D_MODEL + h * 64;

#pragma unroll
    for (int p = 0; p < 4; ++p) {
        int s = p * 256 + tid;
        int r = s >> 3, c = (s & 7) * 8;
        *(uint4*)&sm[r * FPAD + c] = *(const uint4*)(Qf + base + (size_t)(q0 + r) * D_MODEL + c);
    }

    const int arow = (lane & 7) | (((lane >> 3) & 1) << 3);
    const int acol = (lane >> 4) << 3;
    const int brow = (lane & 7) | (((lane >> 4) & 1) << 3);
    const int bcol = ((lane >> 3) & 1) << 3;
    const uint32_t qoff = sb + (uint32_t)(((wid * 16 + arow) * FPAD + acol) * 2);
    const uint32_t koff = (uint32_t)((brow * FPAD + bcol) * 2);
    const int lrow = (lane & 7) + ((lane >> 3) & 1) * 8;
    const int lcol = (lane >> 4) << 3;
    const uint32_t voff = (uint32_t)((lrow * FPAD + lcol) * 2);

    const int ldr = tid >> 3;
    const int ldc = (tid & 7) * 8;

    auto issueKV = [&](int t, int s) {
        const size_t gb = base + (size_t)(t * 64) * D_MODEL;
        const uint32_t sbase = sb + (uint32_t)(FST(s) * 2);
        const __half* srcs[2] = { Kf + gb, Vf + gb };
#pragma unroll
        for (int m = 0; m < 2; ++m)
#pragma unroll
            for (int p = 0; p < 2; ++p) {
                int r = ldr + p * 32;
                cp16(sbase + (uint32_t)((m * 64 * FPAD + r * FPAD + ldc) * 2),
                     srcs[m] + (size_t)r * D_MODEL + ldc);
            }
        CP_COMMIT;
    };

    float m0 = -1e30f, m1 = -1e30f, l0 = 0.f, l1 = 0.f;
    float oacc[8][4];
#pragma unroll
    for (int j = 0; j < 8; ++j)
#pragma unroll
        for (int u = 0; u < 4; ++u) oacc[j][u] = 0.f;

    issueKV(0, 0);
    for (int t = 0; t < SEQ / 64; ++t) {
        const int s = t & 1;
        __syncthreads();
        if (t + 1 < SEQ / 64) { issueKV(t + 1, s ^ 1); CP_WAIT1; } else { CP_WAIT0; }
        __syncthreads();

        const uint32_t kst = sb + (uint32_t)(FST(s) * 2);

        float sc[8][4];
#pragma unroll
        for (int j = 0; j < 8; ++j)
#pragma unroll
            for (int u = 0; u < 4; ++u) sc[j][u] = 0.f;

#pragma unroll
        for (int kg = 0; kg < 4; ++kg) {
            uint32_t af[4];
            LDSM4(af, qoff + kg * 32);
#pragma unroll
            for (int nfp = 0; nfp < 4; ++nfp) {
                uint32_t bf[4];
                LDSM4(bf, kst + koff + (uint32_t)(nfp * 16 * FPAD * 2) + kg * 32);
                mma16816h(sc[2 * nfp],     af, &bf[0]);
                mma16816h(sc[2 * nfp + 1], af, &bf[2]);
            }
        }

        float t0 = -1e30f, t1 = -1e30f;
#pragma unroll
        for (int nf = 0; nf < 8; ++nf) {
            t0 = fmaxf(t0, fmaxf(sc[nf][0], sc[nf][1]));
            t1 = fmaxf(t1, fmaxf(sc[nf][2], sc[nf][3]));
        }
        t0 = fmaxf(t0, __shfl_xor_sync(0xffffffffu, t0, 1));
        t0 = fmaxf(t0, __shfl_xor_sync(0xffffffffu, t0, 2));
        t1 = fmaxf(t1, __shfl_xor_sync(0xffffffffu, t1, 1));
        t1 = fmaxf(t1, __shfl_xor_sync(0xffffffffu, t1, 2));
        float mn0 = fmaxf(m0, t0), mn1 = fmaxf(m1, t1);
        float c0 = __expf(m0 - mn0), c1 = __expf(m1 - mn1);
        m0 = mn0; m1 = mn1;
        float rs0 = 0.f, rs1 = 0.f;
#pragma unroll
        for (int nf = 0; nf < 8; ++nf) {
            sc[nf][0] = __expf(sc[nf][0] - m0);
            sc[nf][1] = __expf(sc[nf][1] - m0);
            sc[nf][2] = __expf(sc[nf][2] - m1);
            sc[nf][3] = __expf(sc[nf][3] - m1);
            rs0 += sc[nf][0] + sc[nf][1];
            rs1 += sc[nf][2] + sc[nf][3];
        }
        rs0 += __shfl_xor_sync(0xffffffffu, rs0, 1);
        rs0 += __shfl_xor_sync(0xffffffffu, rs0, 2);
        rs1 += __shfl_xor_sync(0xffffffffu, rs1, 1);
        rs1 += __shfl_xor_sync(0xffffffffu, rs1, 2);
        l0 = l0 * c0 + rs0;
        l1 = l1 * c1 + rs1;
#pragma unroll
        for (int nf = 0; nf < 8; ++nf) {
            oacc[nf][0] *= c0; oacc[nf][1] *= c0;
            oacc[nf][2] *= c1; oacc[nf][3] *= c1;
        }

        const uint32_t vb = kst + (uint32_t)(64 * FPAD * 2);
#pragma unroll
        for (int kg = 0; kg < 4; ++kg) {
            uint32_t pa[4];
            pa[0] = pack_h(sc[2 * kg][0],     sc[2 * kg][1]);
            pa[1] = pack_h(sc[2 * kg][2],     sc[2 * kg][3]);
            pa[2] = pack_h(sc[2 * kg + 1][0], sc[2 * kg + 1][1]);
            pa[3] = pack_h(sc[2 * kg + 1][2], sc[2 * kg + 1][3]);
            const uint32_t rowoff = voff + (uint32_t)(kg * 16 * FPAD * 2);
#pragma unroll
            for (int nf2 = 0; nf2 < 4; ++nf2) {
                uint32_t bv[4];
                LDSM4T(bv, vb + rowoff + nf2 * 32);
                mma16816h(oacc[2 * nf2],     pa, &bv[0]);
                mma16816h(oacc[2 * nf2 + 1], pa, &bv[2]);
            }
        }
    }

    const float inv0 = 1.f / l0, inv1 = 1.f / l1;
    const int row0 = q0 + wid * 16 + g;
#pragma unroll
    for (int nf = 0; nf < 8; ++nf) {
        const int col = h * 64 + nf * 8 + q4 * 2;
        float v0 = oacc[nf][0] * inv0, v1 = oacc[nf][1] * inv0;
        float v2 = oacc[nf][2] * inv1, v3 = oacc[nf][3] * inv1;
        uint32_t h0, lo0, h1, lo1;
        split_pack2(v0, v1, h0, lo0);
        split_pack2(v2, v3, h1, lo1);
        *(uint32_t*)(Ohi + (size_t)(b * SEQ + row0) * D_MODEL + col) = h0;
        *(uint32_t*)(Olo + (size_t)(b * SEQ + row0) * D_MODEL + col) = lo0;
        *(uint32_t*)(Ohi + (size_t)(b * SEQ + row0 + 8) * D_MODEL + col) = h1;
        *(uint32_t*)(Olo + (size_t)(b * SEQ + row0 + 8) * D_MODEL + col) = lo1;
    }
}

// =================================================================
// Launch
// =================================================================
extern "C" void kernel_launch(void* const* d_in, const int* in_sizes, int n_in,
                              void* d_out, int out_size)
{
    const float* query = (const float*)d_in[0];
    const float* key   = (const float*)d_in[1];
    const float* value = (const float*)d_in[2];
    const float* Wq = (const float*)d_in[3];
    const float* bq = (const float*)d_in[4];
    const float* Wk = (const float*)d_in[5];
    const float* bk = (const float*)d_in[6];
    const float* Wv = (const float*)d_in[7];
    const float* bv = (const float*)d_in[8];
    const float* Wo = (const float*)d_in[9];
    const float* bo = (const float*)d_in[10];
    float* out = (float*)d_out;

    __half *Qf, *Kf, *Vf;
    __nv_bfloat16 *Ahi, *Alo, *Whi, *Wlo;
    cudaGetSymbolAddress((void**)&Qf, g_Qf);
    cudaGetSymbolAddress((void**)&Kf, g_Kf);
    cudaGetSymbolAddress((void**)&Vf, g_Vf);
    cudaGetSymbolAddress((void**)&Ahi, g_Ahi);
    cudaGetSymbolAddress((void**)&Alo, g_Alo);
    cudaGetSymbolAddress((void**)&Whi, g_Whi);
    cudaGetSymbolAddress((void**)&Wlo, g_Wlo);

    static bool attr_done = false;
    if (!attr_done) {
        cudaFuncSetAttribute(gemm_mma, cudaFuncAttributeMaxDynamicSharedMemorySize, GEMM_SMEM);
        cudaFuncSetAttribute(flash_mma, cudaFuncAttributeMaxDynamicSharedMemorySize, FA_SMEM);
        attr_done = true;
    }

    const int nW = D_MODEL * D_MODEL;

    // Wo split (independent; needed by final GEMM)
    split_bf16<<<nW / 1024, 256>>>(Wo, Whi, Wlo, nW);

    // fused Q/K/V projections (fp32 in, fp16 out, Q pre-scaled)
    dim3 pgrid(D_MODEL / 128, M_TOTAL / 128, 3);   // (6, 64, 3)
    gemm_qkv<<<pgrid, 256>>>(query, key, value, Wq, Wk, Wv, bq, bk, bv, Qf, Kf, Vf);

    // attention -> writes (Ahi, Alo) for the final projection
    dim3 agrid(SEQ / 128, NUM_HEADS, BATCH);       // (16, 12, 4)
    flash_mma<<<agrid, 256, FA_SMEM>>>(Qf, Kf, Vf, Ahi, Alo);

    // output projection (3-term bf16 split) -> fp32 out
    dim3 ggrid(D_MODEL / 128, M_TOTAL / 128);      // (6, 64)
    gemm_mma<<<ggrid, 256, GEMM_SMEM>>>(Ahi, Alo, Whi, Wlo, bo, out);
}